// round 6
// baseline (speedup 1.0000x reference)
#include <cuda_runtime.h>
#include <cuda_bf16.h>
#include <cuda_fp16.h>
#include <cstdint>

#define Hh    16
#define Dd    64
#define Nq    1024
#define TPAST 4096
#define TTOT  5120
#define DIMc  1024
#define MID   3072
#define KEEPM 2048
#define SCALE 0.125f
#define SMS   68

// attention smem strides (elements)
#define WSTR 72    // K rows: 144 B
#define VSTR 136   // V^T rows: 272 B

// ---------------- device scratch ----------------
__device__ float g_q [Hh*Nq*Dd];
__device__ float g_kn[Hh*Nq*Dd];
__device__ float g_vn[Hh*Nq*Dd];
__device__ float g_o [Nq*DIMc];
__device__ float g_scores[MID];
__device__ float g_m[Dd];
__device__ int   g_keep[KEEPM];
__device__ __half g_kb [Hh*TTOT*Dd];   // K f16 [h][tok][d]
__device__ __half g_vtb[Hh*Dd*TTOT];   // V^T f16 [h][d][tok]

// ---------------- mma.sync wrapper (f16 in, f32 acc) ----------------
__device__ __forceinline__ void mma_f16(float* d, const uint32_t* a, uint32_t b0, uint32_t b1) {
    asm volatile("mma.sync.aligned.m16n8k16.row.col.f32.f16.f16.f32 "
        "{%0,%1,%2,%3}, {%4,%5,%6,%7}, {%8,%9}, {%0,%1,%2,%3};"
        : "+f"(d[0]), "+f"(d[1]), "+f"(d[2]), "+f"(d[3])
        : "r"(a[0]), "r"(a[1]), "r"(a[2]), "r"(a[3]), "r"(b0), "r"(b1));
}
// accurate exp pair -> packed fp16x2 (2 MUFU + 1 cvt-pack)
__device__ __forceinline__ uint32_t expack(float x, float y) {
    __half2 p = __floats2half2_rn(__expf(x), __expf(y));
    return *reinterpret_cast<uint32_t*>(&p);
}
__device__ __forceinline__ uint32_t packh(float a, float b) {
    __half2 t = __floats2half2_rn(a, b);
    return *reinterpret_cast<uint32_t*>(&t);
}

// ---------------- QKV GEMM (fp32 exact: feeds new_k/new_v + scores) ------
__global__ void gemm_qkv(const float* __restrict__ X,
                         const float* __restrict__ W,
                         const float* __restrict__ bias) {
    __shared__ float As[16][SMS];
    __shared__ float Bs[16][SMS];
    const int j0 = blockIdx.x * 64;
    const int n0 = blockIdx.y * 64;
    const int t  = threadIdx.x;
    const int tr = t >> 4, tc = t & 15;
    const int arow = t >> 2, ac4 = (t & 3) * 4;
    float acc[4][4] = {};
    for (int c0 = 0; c0 < DIMc; c0 += 16) {
        float4 av = *(const float4*)(X + (size_t)(n0 + arow) * DIMc + c0 + ac4);
        float4 bv = *(const float4*)(W + (size_t)(j0 + arow) * DIMc + c0 + ac4);
        As[ac4+0][arow] = av.x; As[ac4+1][arow] = av.y;
        As[ac4+2][arow] = av.z; As[ac4+3][arow] = av.w;
        Bs[ac4+0][arow] = bv.x; Bs[ac4+1][arow] = bv.y;
        Bs[ac4+2][arow] = bv.z; Bs[ac4+3][arow] = bv.w;
        __syncthreads();
        #pragma unroll
        for (int kk = 0; kk < 16; kk++) {
            float4 a = *(const float4*)&As[kk][tr*4];
            float4 b = *(const float4*)&Bs[kk][tc*4];
            acc[0][0] += a.x*b.x; acc[0][1] += a.x*b.y; acc[0][2] += a.x*b.z; acc[0][3] += a.x*b.w;
            acc[1][0] += a.y*b.x; acc[1][1] += a.y*b.y; acc[1][2] += a.y*b.z; acc[1][3] += a.y*b.w;
            acc[2][0] += a.z*b.x; acc[2][1] += a.z*b.y; acc[2][2] += a.z*b.z; acc[2][3] += a.z*b.w;
            acc[3][0] += a.w*b.x; acc[3][1] += a.w*b.y; acc[3][2] += a.w*b.z; acc[3][3] += a.w*b.w;
        }
        __syncthreads();
    }
    const int sec = j0 >> 10;
    const int h   = (j0 >> 6) & 15;
    float* dst = (sec == 0) ? g_q : (sec == 1) ? g_kn : g_vn;
    #pragma unroll
    for (int i = 0; i < 4; i++) {
        const int n = n0 + tr*4 + i;
        #pragma unroll
        for (int j = 0; j < 4; j++) {
            const int d = tc*4 + j;
            dst[(size_t)((h << 10) + n) * 64 + d] = acc[i][j] + bias[j0 + d];
        }
    }
}

// ---------------- output projection GEMM (fp32) ----------------
__global__ void gemm_proj(const float* __restrict__ W,
                          const float* __restrict__ bias,
                          float* __restrict__ C) {
    __shared__ float As[16][SMS];
    __shared__ float Bs[16][SMS];
    const int j0 = blockIdx.x * 64;
    const int n0 = blockIdx.y * 64;
    const int t  = threadIdx.x;
    const int tr = t >> 4, tc = t & 15;
    const int arow = t >> 2, ac4 = (t & 3) * 4;
    float acc[4][4] = {};
    for (int c0 = 0; c0 < DIMc; c0 += 16) {
        float4 av = *(const float4*)(g_o + (size_t)(n0 + arow) * DIMc + c0 + ac4);
        float4 bv = *(const float4*)(W   + (size_t)(j0 + arow) * DIMc + c0 + ac4);
        As[ac4+0][arow] = av.x; As[ac4+1][arow] = av.y;
        As[ac4+2][arow] = av.z; As[ac4+3][arow] = av.w;
        Bs[ac4+0][arow] = bv.x; Bs[ac4+1][arow] = bv.y;
        Bs[ac4+2][arow] = bv.z; Bs[ac4+3][arow] = bv.w;
        __syncthreads();
        #pragma unroll
        for (int kk = 0; kk < 16; kk++) {
            float4 a = *(const float4*)&As[kk][tr*4];
            float4 b = *(const float4*)&Bs[kk][tc*4];
            acc[0][0] += a.x*b.x; acc[0][1] += a.x*b.y; acc[0][2] += a.x*b.z; acc[0][3] += a.x*b.w;
            acc[1][0] += a.y*b.x; acc[1][1] += a.y*b.y; acc[1][2] += a.y*b.z; acc[1][3] += a.y*b.w;
            acc[2][0] += a.z*b.x; acc[2][1] += a.z*b.y; acc[2][2] += a.z*b.z; acc[2][3] += a.z*b.w;
            acc[3][0] += a.w*b.x; acc[3][1] += a.w*b.y; acc[3][2] += a.w*b.z; acc[3][3] += a.w*b.w;
        }
        __syncthreads();
    }
    #pragma unroll
    for (int i = 0; i < 4; i++) {
        const int n = n0 + tr*4 + i;
        #pragma unroll
        for (int j = 0; j < 4; j++) {
            const int jg = j0 + tc*4 + j;
            C[(size_t)n * DIMc + jg] = acc[i][j] + bias[jg];
        }
    }
}

// ---------------- K -> f16 convert: [h][tok][d], 128 toks per block -------
__global__ void conv_k(const float* __restrict__ pk) {
    const int h = blockIdx.y, t0 = blockIdx.x * 128;
    const float* src = (t0 < TPAST) ? pk + ((size_t)h * TPAST + t0) * 64
                                    : g_kn + ((size_t)(h << 10) + (t0 - TPAST)) * 64;
    uint32_t* dst = reinterpret_cast<uint32_t*>(g_kb + ((size_t)h * TTOT + t0) * 64);
    const int t = threadIdx.x;
    #pragma unroll
    for (int q = 0; q < 8; q++) {
        int f = q * 256 + t;                     // 2048 float4s
        float4 v = *(const float4*)(src + (size_t)f * 4);
        dst[2*f]   = packh(v.x, v.y);
        dst[2*f+1] = packh(v.z, v.w);
    }
}

// ---------------- V -> f16 transposed: [h][d][tok], 64 toks per block ------
__global__ void conv_vt(const float* __restrict__ pv) {
    __shared__ float ts[64][65];
    const int h = blockIdx.y, t0 = blockIdx.x * 64;
    const float* src = (t0 < TPAST) ? pv + ((size_t)h * TPAST + t0) * 64
                                    : g_vn + ((size_t)(h << 10) + (t0 - TPAST)) * 64;
    const int t = threadIdx.x;
    #pragma unroll
    for (int q = 0; q < 4; q++) {
        int f = q * 256 + t;                     // 1024 float4s = 64x64
        int tok = f >> 4, d4 = (f & 15) * 4;
        float4 v = *(const float4*)(src + (size_t)tok * 64 + d4);
        ts[tok][d4+0] = v.x; ts[tok][d4+1] = v.y; ts[tok][d4+2] = v.z; ts[tok][d4+3] = v.w;
    }
    __syncthreads();
    const int d = t >> 2, c0 = (t & 3) * 16;
    uint32_t* orow = reinterpret_cast<uint32_t*>(g_vtb + ((size_t)h * 64 + d) * TTOT + t0);
    #pragma unroll
    for (int k = 0; k < 8; k++) {
        int tok = c0 + 2 * k;
        orow[c0/2 + k] = packh(ts[tok][d], ts[tok+1][d]);
    }
}

// ---------------- attention: mma.sync flash kernel ----------------
// grid (8,16): 128 q rows per CTA, 8 warps x 16 rows; 40 KV tiles of 128.
__global__ void __launch_bounds__(256, 1)
attn_mma(const __half* __restrict__ kb, const __half* __restrict__ vtb) {
    __shared__ __half Ks[128 * WSTR];
    __shared__ __half VTs[72 * VSTR];
    const int t = threadIdx.x, lane = t & 31, w = t >> 5;
    const int h = blockIdx.y, n0 = blockIdx.x * 128;
    const int g = lane >> 2, i = lane & 3;

    // ones column rows (d=64 ones, 65..71 zero) for rowsum-via-MMA
    for (int f = t; f < 8 * 128; f += 256) {
        int r = f >> 7, c = f & 127;
        VTs[(64 + r) * VSTR + c] = (r == 0) ? __float2half(1.0f) : __float2half(0.0f);
    }

    // Q fragments (f16, pre-scaled), resident all kernel
    uint32_t qa[4][4];
    {
        const float* qb = g_q + (size_t)((h << 10) + n0 + 16 * w) * 64;
        #pragma unroll
        for (int ks = 0; ks < 4; ks++) {
            float2 x0 = *(const float2*)(qb + g * 64 + 16 * ks + 2 * i);
            float2 x1 = *(const float2*)(qb + g * 64 + 16 * ks + 8 + 2 * i);
            float2 x2 = *(const float2*)(qb + (g + 8) * 64 + 16 * ks + 2 * i);
            float2 x3 = *(const float2*)(qb + (g + 8) * 64 + 16 * ks + 8 + 2 * i);
            qa[ks][0] = packh(x0.x * SCALE, x0.y * SCALE);
            qa[ks][1] = packh(x2.x * SCALE, x2.y * SCALE);
            qa[ks][2] = packh(x1.x * SCALE, x1.y * SCALE);
            qa[ks][3] = packh(x3.x * SCALE, x3.y * SCALE);
        }
    }

    const __half* kbh = kb + (size_t)h * TTOT * 64;
    const __half* vth = vtb + (size_t)h * 64 * TTOT;

    float o[9][4];
    #pragma unroll
    for (int nd = 0; nd < 9; nd++)
        #pragma unroll
        for (int c = 0; c < 4; c++) o[nd][c] = 0.0f;

    // prefetch tile 0
    uint4 pk[4], pv[4];
    {
        const uint4* s = (const uint4*)kbh;
        #pragma unroll
        for (int q = 0; q < 4; q++) pk[q] = s[q * 256 + t];
        #pragma unroll
        for (int q = 0; q < 4; q++) {
            int f = q * 256 + t, d = f >> 4, c = f & 15;
            pv[q] = *(const uint4*)(vth + (size_t)d * TTOT + c * 8);
        }
    }

    for (int kt = 0; kt < 40; kt++) {
        __syncthreads();
        #pragma unroll
        for (int q = 0; q < 4; q++) {
            int f = q * 256 + t, tok = f >> 3, dc = f & 7;
            *(uint4*)((char*)Ks + tok * 144 + dc * 16) = pk[q];
        }
        #pragma unroll
        for (int q = 0; q < 4; q++) {
            int f = q * 256 + t, d = f >> 4, c = f & 15;
            *(uint4*)((char*)VTs + d * 272 + c * 16) = pv[q];
        }
        __syncthreads();
        if (kt < 39) {
            const uint4* s = (const uint4*)(kbh + (size_t)(kt + 1) * 128 * 64);
            #pragma unroll
            for (int q = 0; q < 4; q++) pk[q] = s[q * 256 + t];
            #pragma unroll
            for (int q = 0; q < 4; q++) {
                int f = q * 256 + t, d = f >> 4, c = f & 15;
                pv[q] = *(const uint4*)(vth + (size_t)d * TTOT + (kt + 1) * 128 + c * 8);
            }
        }

        // S = Q K^T : 16 token-blocks x 4 k-steps (f16 MMA, f32 acc)
        float s[16][4];
        #pragma unroll
        for (int nb = 0; nb < 16; nb++) {
            s[nb][0] = s[nb][1] = s[nb][2] = s[nb][3] = 0.0f;
            const char* kr = (const char*)Ks + (nb * 8 + g) * 144 + i * 4;
            #pragma unroll
            for (int ks = 0; ks < 4; ks++) {
                uint32_t b0 = *(const uint32_t*)(kr + ks * 32);
                uint32_t b1 = *(const uint32_t*)(kr + ks * 32 + 16);
                mma_f16(s[nb], qa[ks], b0, b1);
            }
        }
        // P = exp(S) (accurate MUFU); O += P V  (9 d-blocks incl. rowsum col)
        #pragma unroll
        for (int ks = 0; ks < 8; ks++) {
            uint32_t pa[4];
            pa[0] = expack(s[2*ks][0],   s[2*ks][1]);
            pa[1] = expack(s[2*ks][2],   s[2*ks][3]);
            pa[2] = expack(s[2*ks+1][0], s[2*ks+1][1]);
            pa[3] = expack(s[2*ks+1][2], s[2*ks+1][3]);
            const char* vr = (const char*)VTs + g * 272 + i * 4 + ks * 32;
            #pragma unroll
            for (int nd = 0; nd < 9; nd++) {
                uint32_t b0 = *(const uint32_t*)(vr + nd * 8 * 272);
                uint32_t b1 = *(const uint32_t*)(vr + nd * 8 * 272 + 16);
                mma_f16(o[nd], pa, b0, b1);
            }
        }
    }

    // epilogue: divide by rowsum (col 64), write g_o
    float lpg  = __shfl_sync(0xffffffffu, o[8][0], lane & ~3);
    float lpg8 = __shfl_sync(0xffffffffu, o[8][2], lane & ~3);
    float invg = 1.0f / lpg, inv8 = 1.0f / lpg8;
    const int r0 = n0 + 16 * w + g;
    float* ob = g_o + (size_t)r0 * DIMc + (h << 6) + 2 * i;
    #pragma unroll
    for (int nd = 0; nd < 8; nd++) {
        float2 w0 = make_float2(o[nd][0] * invg, o[nd][1] * invg);
        float2 w1 = make_float2(o[nd][2] * inv8, o[nd][3] * inv8);
        *(float2*)(ob + nd * 8)              = w0;
        *(float2*)(ob + 8 * DIMc + nd * 8)   = w1;
    }
}

// ---------------- pruning ----------------
__global__ void compute_m() {
    const int t = threadIdx.x;
    const int d = t & 63, g = t >> 6;
    float acc = 0.0f;
    for (int row = g; row < Hh * Nq; row += 4) {
        int n = row & (Nq - 1);
        float w = (n < 5) ? 1.0f : (n < 1013 ? (1.0f / 16.0f) : (1.0f / 11.0f));
        acc += w * g_q[(size_t)row * 64 + d];
    }
    __shared__ float red[256];
    red[t] = acc;
    __syncthreads();
    if (g == 0)
        g_m[d] = (red[d] + red[64 + d] + red[128 + d] + red[192 + d]) * (1.0f / (69.0f * 16.0f));
}

__global__ void compute_scores(const float* __restrict__ pk) {
    __shared__ float m[64];
    if (threadIdx.x < 64) m[threadIdx.x] = g_m[threadIdx.x];
    __syncthreads();
    const int p = blockIdx.x * 256 + threadIdx.x;
    float acc = 0.0f;
    for (int h = 0; h < Hh; h++) {
        const float* kr = pk + (size_t)(h * TPAST + 1024 + p) * 64;
        #pragma unroll
        for (int d = 0; d < 64; d++) acc += m[d] * kr[d];
    }
    g_scores[p] = acc * (1.0f / 16.0f);
}

// ---- exact top-2048 via 64-bit bitwise radix select (keys unique) ----
__device__ __forceinline__ unsigned long long score_key(float s, int p) {
    unsigned u = __float_as_uint(s);
    u = (u & 0x80000000u) ? ~u : (u | 0x80000000u);
    return ((unsigned long long)u << 32) | (unsigned)(0xFFFFFFFFu - p);
}

__global__ void select_topk() {
    __shared__ int cnt[64];
    __shared__ int scan[1024];
    const int t = threadIdx.x, lid = t & 31;
    unsigned long long k[3];
    #pragma unroll
    for (int q = 0; q < 3; q++) k[q] = score_key(g_scores[t*3+q], t*3+q);
    if (t < 64) cnt[t] = 0;
    __syncthreads();
    unsigned long long prefix = 0;
    for (int b = 63; b >= 0; b--) {
        unsigned long long cand = prefix | (1ULL << b);
        int c = (int)(k[0] >= cand) + (int)(k[1] >= cand) + (int)(k[2] >= cand);
        #pragma unroll
        for (int o = 16; o; o >>= 1) c += __shfl_xor_sync(0xffffffffu, c, o);
        if (lid == 0) atomicAdd(&cnt[b], c);
        __syncthreads();
        if (cnt[b] >= KEEPM) prefix = cand;
    }
    bool kp[3]; int c2 = 0;
    #pragma unroll
    for (int q = 0; q < 3; q++) { kp[q] = (k[q] >= prefix); c2 += kp[q] ? 1 : 0; }
    scan[t] = c2;
    __syncthreads();
    for (int off = 1; off < 1024; off <<= 1) {
        int v = (t >= off) ? scan[t - off] : 0;
        __syncthreads();
        scan[t] += v;
        __syncthreads();
    }
    int pos = scan[t] - c2;
    #pragma unroll
    for (int q = 0; q < 3; q++)
        if (kp[q]) g_keep[pos++] = 1024 + t*3 + q;
}

// ---------------- gather pruned KV ----------------
__global__ void gather_kv(const float* __restrict__ pk, const float* __restrict__ pv,
                          float* __restrict__ nk, float* __restrict__ nv) {
    const int rowid = blockIdx.x * 16 + (threadIdx.x >> 4);
    const int d4 = (threadIdx.x & 15) * 4;
    const int h = rowid >> 12;
    const int r = rowid & 4095;
    const int idx = (r < 1024) ? r : ((r < 3072) ? g_keep[r - 1024] : r + 1024);
    const float* ks; const float* vs;
    if (idx < TPAST) {
        ks = pk + (size_t)(h * TPAST + idx) * 64;
        vs = pv + (size_t)(h * TPAST + idx) * 64;
    } else {
        ks = g_kn + (size_t)((h << 10) + (idx - TPAST)) * 64;
        vs = g_vn + (size_t)((h << 10) + (idx - TPAST)) * 64;
    }
    *(float4*)(nk + (size_t)rowid * 64 + d4) = *(const float4*)(ks + d4);
    *(float4*)(nv + (size_t)rowid * 64 + d4) = *(const float4*)(vs + d4);
}

// ---------------- launch ----------------
extern "C" void kernel_launch(void* const* d_in, const int* in_sizes, int n_in,
                              void* d_out, int out_size) {
    const float* x      = (const float*)d_in[0];
    const float* past_k = (const float*)d_in[1];
    const float* past_v = (const float*)d_in[2];
    const float* qkv_w  = (const float*)d_in[3];
    const float* qkv_b  = (const float*)d_in[4];
    const float* proj_w = (const float*)d_in[5];
    const float* proj_b = (const float*)d_in[6];

    float* out = (float*)d_out;
    float* nk  = out + (size_t)Nq * DIMc;
    float* nv  = nk + (size_t)Hh * 4096 * 64;

    __half* kb;  cudaGetSymbolAddress((void**)&kb, g_kb);
    __half* vtb; cudaGetSymbolAddress((void**)&vtb, g_vtb);

    gemm_qkv<<<dim3(48, 16), 256>>>(x, qkv_w, qkv_b);
    conv_k<<<dim3(40, 16), 256>>>(past_k);
    conv_vt<<<dim3(80, 16), 256>>>(past_v);
    compute_m<<<1, 256>>>();
    compute_scores<<<12, 256>>>(past_k);
    select_topk<<<1, 1024>>>();
    gather_kv<<<4096, 256>>>(past_k, past_v, nk, nv);
    attn_mma<<<dim3(8, 16), 256>>>(kb, vtb);
    gemm_proj<<<dim3(16, 16), 256>>>(proj_w, proj_b, out);
}

// round 8
// speedup vs baseline: 2.7149x; 2.7149x over previous
#include <cuda_runtime.h>
#include <cuda_bf16.h>
#include <cuda_fp16.h>
#include <cstdint>

#define Hh    16
#define Dd    64
#define Nq    1024
#define TPAST 4096
#define TTOT  5120
#define DIMc  1024
#define MID   3072
#define KEEPM 2048
#define SCALE 0.125f
#define SMS   68

#define WSTR 72    // K rows: 144 B
#define VSTR 136   // V^T rows: 272 B

// ---------------- device scratch ----------------
__device__ float g_q [Hh*Nq*Dd];
__device__ float g_kn[Hh*Nq*Dd];
__device__ float g_vn[Hh*Nq*Dd];
__device__ float g_o [Nq*DIMc];
__device__ float g_scores[MID];
__device__ float g_m[Dd];
__device__ float g_mp[64*64];
__device__ float g_sp[16*3072];
__device__ int   g_keep[KEEPM];
__device__ __half g_kb  [Hh*TTOT*Dd];   // K f16 [h][tok][d]
__device__ __half g_vtb [Hh*Dd*TTOT];   // V^T f16 [h][d][tok]
__device__ __half g_x16 [Nq*DIMc];      // x in f16
__device__ __half g_w16 [2048*DIMc];    // k,v weight rows in f16
__device__ __half g_pw16[DIMc*DIMc];    // proj_w in f16
__device__ __half g_o16 [Nq*DIMc];      // attn out in f16

// ---------------- helpers ----------------
__device__ __forceinline__ void mma_f16(float* d, const uint32_t* a, uint32_t b0, uint32_t b1) {
    asm volatile("mma.sync.aligned.m16n8k16.row.col.f32.f16.f16.f32 "
        "{%0,%1,%2,%3}, {%4,%5,%6,%7}, {%8,%9}, {%0,%1,%2,%3};"
        : "+f"(d[0]), "+f"(d[1]), "+f"(d[2]), "+f"(d[3])
        : "r"(a[0]), "r"(a[1]), "r"(a[2]), "r"(a[3]), "r"(b0), "r"(b1));
}
__device__ __forceinline__ uint32_t expack(float x, float y) {
    __half2 p = __floats2half2_rn(__expf(x), __expf(y));
    return *reinterpret_cast<uint32_t*>(&p);
}
__device__ __forceinline__ uint32_t packh(float a, float b) {
    __half2 t = __floats2half2_rn(a, b);
    return *reinterpret_cast<uint32_t*>(&t);
}

// ---------------- generic fp32 -> f16 (count = grid*256*4 elems) ---------
__global__ void conv_f2h(const float* __restrict__ s, __half* __restrict__ d) {
    int f = blockIdx.x * 256 + threadIdx.x;
    float4 v = *(const float4*)(s + (size_t)f * 4);
    *(uint2*)((char*)d + (size_t)f * 8) = make_uint2(packh(v.x, v.y), packh(v.z, v.w));
}
// g_o -> g_o16 using device-side symbol access (no host symbol address!)
__global__ void conv_o() {
    int f = blockIdx.x * 256 + threadIdx.x;
    float4 v = *(const float4*)(g_o + (size_t)f * 4);
    *(uint2*)((char*)g_o16 + (size_t)f * 8) = make_uint2(packh(v.x, v.y), packh(v.z, v.w));
}

// ---------------- Q-only GEMM (fp32 exact: feeds top-k path) -------------
__global__ void gemm_q(const float* __restrict__ X,
                       const float* __restrict__ W,
                       const float* __restrict__ bias) {
    __shared__ float As[16][SMS];
    __shared__ float Bs[16][SMS];
    const int j0 = blockIdx.x * 64;       // < 1024: q section only
    const int n0 = blockIdx.y * 64;
    const int t  = threadIdx.x;
    const int tr = t >> 4, tc = t & 15;
    const int arow = t >> 2, ac4 = (t & 3) * 4;
    float acc[4][4] = {};
    for (int c0 = 0; c0 < DIMc; c0 += 16) {
        float4 av = *(const float4*)(X + (size_t)(n0 + arow) * DIMc + c0 + ac4);
        float4 bv = *(const float4*)(W + (size_t)(j0 + arow) * DIMc + c0 + ac4);
        As[ac4+0][arow] = av.x; As[ac4+1][arow] = av.y;
        As[ac4+2][arow] = av.z; As[ac4+3][arow] = av.w;
        Bs[ac4+0][arow] = bv.x; Bs[ac4+1][arow] = bv.y;
        Bs[ac4+2][arow] = bv.z; Bs[ac4+3][arow] = bv.w;
        __syncthreads();
        #pragma unroll
        for (int kk = 0; kk < 16; kk++) {
            float4 a = *(const float4*)&As[kk][tr*4];
            float4 b = *(const float4*)&Bs[kk][tc*4];
            acc[0][0] += a.x*b.x; acc[0][1] += a.x*b.y; acc[0][2] += a.x*b.z; acc[0][3] += a.x*b.w;
            acc[1][0] += a.y*b.x; acc[1][1] += a.y*b.y; acc[1][2] += a.y*b.z; acc[1][3] += a.y*b.w;
            acc[2][0] += a.z*b.x; acc[2][1] += a.z*b.y; acc[2][2] += a.z*b.z; acc[2][3] += a.z*b.w;
            acc[3][0] += a.w*b.x; acc[3][1] += a.w*b.y; acc[3][2] += a.w*b.z; acc[3][3] += a.w*b.w;
        }
        __syncthreads();
    }
    const int h = j0 >> 6;
    #pragma unroll
    for (int i = 0; i < 4; i++) {
        const int n = n0 + tr*4 + i;
        #pragma unroll
        for (int j = 0; j < 4; j++) {
            const int d = tc*4 + j;
            g_q[(size_t)((h << 10) + n) * 64 + d] = acc[i][j] + bias[j0 + d];
        }
    }
}

// ---------------- f16 tensor-core GEMM: C[n][j] = A[n]·B[j] + bias -------
// A [M][1024] f16 row-major, B [N][1024] f16 row-major. 128x64 tile, 8 warps.
// mode 0: linear C (stride 1024). mode 1: scatter to g_kn/g_vn (kv section).
__global__ void __launch_bounds__(256) gemm_h16(
    const __half* __restrict__ A, const __half* __restrict__ B,
    const float* __restrict__ bias, float* __restrict__ C, int mode)
{
    __shared__ __half As[128 * 72];
    __shared__ __half Bs[64 * 72];
    const int t = threadIdx.x, lane = t & 31, w = t >> 5;
    const int j0 = blockIdx.x * 64, n0 = blockIdx.y * 128;
    const int g = lane >> 2, i = lane & 3;
    float acc[8][4] = {};
    const uint4* Ag = (const uint4*)(A + (size_t)n0 * 1024);
    const uint4* Bg = (const uint4*)(B + (size_t)j0 * 1024);

    uint4 pa[4], pb[2];
    #pragma unroll
    for (int q = 0; q < 4; q++) { int f = q*256+t; pa[q] = Ag[(size_t)(f>>3)*128 + (f&7)]; }
    #pragma unroll
    for (int q = 0; q < 2; q++) { int f = q*256+t; pb[q] = Bg[(size_t)(f>>3)*128 + (f&7)]; }

    for (int c = 0; c < 16; c++) {
        __syncthreads();
        #pragma unroll
        for (int q = 0; q < 4; q++) { int f = q*256+t; *(uint4*)((char*)As + (f>>3)*144 + (f&7)*16) = pa[q]; }
        #pragma unroll
        for (int q = 0; q < 2; q++) { int f = q*256+t; *(uint4*)((char*)Bs + (f>>3)*144 + (f&7)*16) = pb[q]; }
        __syncthreads();
        if (c < 15) {
            #pragma unroll
            for (int q = 0; q < 4; q++) { int f = q*256+t; pa[q] = Ag[(size_t)(f>>3)*128 + (c+1)*8 + (f&7)]; }
            #pragma unroll
            for (int q = 0; q < 2; q++) { int f = q*256+t; pb[q] = Bg[(size_t)(f>>3)*128 + (c+1)*8 + (f&7)]; }
        }
        const uint32_t* Aw = (const uint32_t*)As;
        #pragma unroll
        for (int ks = 0; ks < 4; ks++) {
            uint32_t a[4];
            a[0] = Aw[(16*w + g)     * 36 + ks*8 + i];
            a[1] = Aw[(16*w + g + 8) * 36 + ks*8 + i];
            a[2] = Aw[(16*w + g)     * 36 + ks*8 + 4 + i];
            a[3] = Aw[(16*w + g + 8) * 36 + ks*8 + 4 + i];
            #pragma unroll
            for (int nb = 0; nb < 8; nb++) {
                const char* br = (const char*)Bs + (nb*8 + g)*144 + i*4 + ks*32;
                uint32_t b0 = *(const uint32_t*)br;
                uint32_t b1 = *(const uint32_t*)(br + 16);
                mma_f16(acc[nb], a, b0, b1);
            }
        }
    }
    const int r0 = n0 + 16*w + g;
    #pragma unroll
    for (int nb = 0; nb < 8; nb++) {
        int col = j0 + nb*8 + 2*i;
        float2 bv = *(const float2*)(bias + col);
        float2 w0 = make_float2(acc[nb][0] + bv.x, acc[nb][1] + bv.y);
        float2 w1 = make_float2(acc[nb][2] + bv.x, acc[nb][3] + bv.y);
        if (mode == 0) {
            *(float2*)(C + (size_t)r0 * 1024 + col)       = w0;
            *(float2*)(C + (size_t)(r0 + 8) * 1024 + col) = w1;
        } else {
            float* dst = (col < 1024) ? g_kn : g_vn;
            int h = (col >> 6) & 15, d = col & 63;
            *(float2*)(dst + (size_t)((h << 10) + r0) * 64 + d)     = w0;
            *(float2*)(dst + (size_t)((h << 10) + r0 + 8) * 64 + d) = w1;
        }
    }
}

// ---------------- K -> f16 [h][tok][d] ----------------
__global__ void conv_k(const float* __restrict__ pk) {
    const int h = blockIdx.y, t0 = blockIdx.x * 128;
    const float* src = (t0 < TPAST) ? pk + ((size_t)h * TPAST + t0) * 64
                                    : g_kn + ((size_t)(h << 10) + (t0 - TPAST)) * 64;
    uint32_t* dst = reinterpret_cast<uint32_t*>(g_kb + ((size_t)h * TTOT + t0) * 64);
    const int t = threadIdx.x;
    #pragma unroll
    for (int q = 0; q < 8; q++) {
        int f = q * 256 + t;
        float4 v = *(const float4*)(src + (size_t)f * 4);
        dst[2*f]   = packh(v.x, v.y);
        dst[2*f+1] = packh(v.z, v.w);
    }
}

// ---------------- V -> f16 transposed [h][d][tok] ----------------
__global__ void conv_vt(const float* __restrict__ pv) {
    __shared__ float ts[64][65];
    const int h = blockIdx.y, t0 = blockIdx.x * 64;
    const float* src = (t0 < TPAST) ? pv + ((size_t)h * TPAST + t0) * 64
                                    : g_vn + ((size_t)(h << 10) + (t0 - TPAST)) * 64;
    const int t = threadIdx.x;
    #pragma unroll
    for (int q = 0; q < 4; q++) {
        int f = q * 256 + t;
        int tok = f >> 4, d4 = (f & 15) * 4;
        float4 v = *(const float4*)(src + (size_t)tok * 64 + d4);
        ts[tok][d4+0] = v.x; ts[tok][d4+1] = v.y; ts[tok][d4+2] = v.z; ts[tok][d4+3] = v.w;
    }
    __syncthreads();
    const int d = t >> 2, c0 = (t & 3) * 16;
    uint32_t* orow = reinterpret_cast<uint32_t*>(g_vtb + ((size_t)h * 64 + d) * TTOT + t0);
    #pragma unroll
    for (int k = 0; k < 8; k++) {
        int tok = c0 + 2 * k;
        orow[c0/2 + k] = packh(ts[tok][d], ts[tok+1][d]);
    }
}

// ---------------- attention: mma.sync flash kernel ----------
__global__ void __launch_bounds__(256, 1)
attn_mma(const __half* __restrict__ kb, const __half* __restrict__ vtb) {
    __shared__ __half Ks[128 * WSTR];
    __shared__ __half VTs[72 * VSTR];
    const int t = threadIdx.x, lane = t & 31, w = t >> 5;
    const int h = blockIdx.y, n0 = blockIdx.x * 128;
    const int g = lane >> 2, i = lane & 3;

    for (int f = t; f < 8 * 128; f += 256) {
        int r = f >> 7, c = f & 127;
        VTs[(64 + r) * VSTR + c] = (r == 0) ? __float2half(1.0f) : __float2half(0.0f);
    }

    uint32_t qa[4][4];
    {
        const float* qb = g_q + (size_t)((h << 10) + n0 + 16 * w) * 64;
        #pragma unroll
        for (int ks = 0; ks < 4; ks++) {
            float2 x0 = *(const float2*)(qb + g * 64 + 16 * ks + 2 * i);
            float2 x1 = *(const float2*)(qb + g * 64 + 16 * ks + 8 + 2 * i);
            float2 x2 = *(const float2*)(qb + (g + 8) * 64 + 16 * ks + 2 * i);
            float2 x3 = *(const float2*)(qb + (g + 8) * 64 + 16 * ks + 8 + 2 * i);
            qa[ks][0] = packh(x0.x * SCALE, x0.y * SCALE);
            qa[ks][1] = packh(x2.x * SCALE, x2.y * SCALE);
            qa[ks][2] = packh(x1.x * SCALE, x1.y * SCALE);
            qa[ks][3] = packh(x3.x * SCALE, x3.y * SCALE);
        }
    }

    const __half* kbh = kb + (size_t)h * TTOT * 64;
    const __half* vth = vtb + (size_t)h * 64 * TTOT;

    float o[9][4];
    #pragma unroll
    for (int nd = 0; nd < 9; nd++)
        #pragma unroll
        for (int c = 0; c < 4; c++) o[nd][c] = 0.0f;

    uint4 pk[4], pv[4];
    {
        const uint4* s = (const uint4*)kbh;
        #pragma unroll
        for (int q = 0; q < 4; q++) pk[q] = s[q * 256 + t];
        #pragma unroll
        for (int q = 0; q < 4; q++) {
            int f = q * 256 + t, d = f >> 4, c = f & 15;
            pv[q] = *(const uint4*)(vth + (size_t)d * TTOT + c * 8);
        }
    }

    for (int kt = 0; kt < 40; kt++) {
        __syncthreads();
        #pragma unroll
        for (int q = 0; q < 4; q++) {
            int f = q * 256 + t, tok = f >> 3, dc = f & 7;
            *(uint4*)((char*)Ks + tok * 144 + dc * 16) = pk[q];
        }
        #pragma unroll
        for (int q = 0; q < 4; q++) {
            int f = q * 256 + t, d = f >> 4, c = f & 15;
            *(uint4*)((char*)VTs + d * 272 + c * 16) = pv[q];
        }
        __syncthreads();
        if (kt < 39) {
            const uint4* s = (const uint4*)(kbh + (size_t)(kt + 1) * 128 * 64);
            #pragma unroll
            for (int q = 0; q < 4; q++) pk[q] = s[q * 256 + t];
            #pragma unroll
            for (int q = 0; q < 4; q++) {
                int f = q * 256 + t, d = f >> 4, c = f & 15;
                pv[q] = *(const uint4*)(vth + (size_t)d * TTOT + (kt + 1) * 128 + c * 8);
            }
        }

        float s[16][4];
        #pragma unroll
        for (int nb = 0; nb < 16; nb++) {
            s[nb][0] = s[nb][1] = s[nb][2] = s[nb][3] = 0.0f;
            const char* kr = (const char*)Ks + (nb * 8 + g) * 144 + i * 4;
            #pragma unroll
            for (int ks = 0; ks < 4; ks++) {
                uint32_t b0 = *(const uint32_t*)(kr + ks * 32);
                uint32_t b1 = *(const uint32_t*)(kr + ks * 32 + 16);
                mma_f16(s[nb], qa[ks], b0, b1);
            }
        }
        #pragma unroll
        for (int ks = 0; ks < 8; ks++) {
            uint32_t pa[4];
            pa[0] = expack(s[2*ks][0],   s[2*ks][1]);
            pa[1] = expack(s[2*ks][2],   s[2*ks][3]);
            pa[2] = expack(s[2*ks+1][0], s[2*ks+1][1]);
            pa[3] = expack(s[2*ks+1][2], s[2*ks+1][3]);
            const char* vr = (const char*)VTs + g * 272 + i * 4 + ks * 32;
            #pragma unroll
            for (int nd = 0; nd < 9; nd++) {
                uint32_t b0 = *(const uint32_t*)(vr + nd * 8 * 272);
                uint32_t b1 = *(const uint32_t*)(vr + nd * 8 * 272 + 16);
                mma_f16(o[nd], pa, b0, b1);
            }
        }
    }

    float lpg  = __shfl_sync(0xffffffffu, o[8][0], lane & ~3);
    float lpg8 = __shfl_sync(0xffffffffu, o[8][2], lane & ~3);
    float invg = 1.0f / lpg, inv8 = 1.0f / lpg8;
    const int r0 = n0 + 16 * w + g;
    float* ob = g_o + (size_t)r0 * DIMc + (h << 6) + 2 * i;
    #pragma unroll
    for (int nd = 0; nd < 8; nd++) {
        float2 w0 = make_float2(o[nd][0] * invg, o[nd][1] * invg);
        float2 w1 = make_float2(o[nd][2] * inv8, o[nd][3] * inv8);
        *(float2*)(ob + nd * 8)            = w0;
        *(float2*)(ob + 8 * DIMc + nd * 8) = w1;
    }
}

// ---------------- pruning: parallel weighted mean ----------------
__global__ void compute_m1() {
    const int t = threadIdx.x, b = blockIdx.x;
    const int d = t & 63, grp = t >> 6;
    float acc = 0.0f;
    for (int r = grp; r < 256; r += 4) {
        int row = b * 256 + r;
        int n = row & (Nq - 1);
        float w = (n < 5) ? 1.0f : (n < 1013 ? (1.0f / 16.0f) : (1.0f / 11.0f));
        acc += w * g_q[(size_t)row * 64 + d];
    }
    __shared__ float red[256];
    red[t] = acc;
    __syncthreads();
    if (grp == 0)
        g_mp[b * 64 + d] = red[d] + red[64 + d] + red[128 + d] + red[192 + d];
}
__global__ void compute_m2() {
    const int d = threadIdx.x;
    float a = 0.0f;
    for (int b = 0; b < 64; b++) a += g_mp[b * 64 + d];
    g_m[d] = a * (1.0f / (69.0f * 16.0f));
}

// ---------------- scores: per-(head, pos) partials then reduce ----------
__global__ void scores1(const float* __restrict__ pk) {
    __shared__ float m[64];
    if (threadIdx.x < 64) m[threadIdx.x] = g_m[threadIdx.x];
    __syncthreads();
    const int p = blockIdx.x * 256 + threadIdx.x, h = blockIdx.y;
    const float* kr = pk + (size_t)(h * TPAST + 1024 + p) * 64;
    float acc = 0.0f;
    #pragma unroll
    for (int d = 0; d < 64; d += 4) {
        float4 v = *(const float4*)(kr + d);
        acc += m[d] * v.x + m[d+1] * v.y + m[d+2] * v.z + m[d+3] * v.w;
    }
    g_sp[h * 3072 + p] = acc;
}
__global__ void scores2() {
    const int p = blockIdx.x * 1024 + threadIdx.x;
    float a = 0.0f;
    #pragma unroll
    for (int h = 0; h < 16; h++) a += g_sp[h * 3072 + p];
    g_scores[p] = a * (1.0f / 16.0f);
}

// ---- exact top-2048 via 64-bit bitwise radix select (keys unique) ----
__device__ __forceinline__ unsigned long long score_key(float s, int p) {
    unsigned u = __float_as_uint(s);
    u = (u & 0x80000000u) ? ~u : (u | 0x80000000u);
    return ((unsigned long long)u << 32) | (unsigned)(0xFFFFFFFFu - p);
}

__global__ void select_topk() {
    __shared__ int cnt[64];
    __shared__ int scan[1024];
    const int t = threadIdx.x, lid = t & 31;
    unsigned long long k[3];
    #pragma unroll
    for (int q = 0; q < 3; q++) k[q] = score_key(g_scores[t*3+q], t*3+q);
    if (t < 64) cnt[t] = 0;
    __syncthreads();
    unsigned long long prefix = 0;
    for (int b = 63; b >= 0; b--) {
        unsigned long long cand = prefix | (1ULL << b);
        int c = (int)(k[0] >= cand) + (int)(k[1] >= cand) + (int)(k[2] >= cand);
        #pragma unroll
        for (int o = 16; o; o >>= 1) c += __shfl_xor_sync(0xffffffffu, c, o);
        if (lid == 0) atomicAdd(&cnt[b], c);
        __syncthreads();
        if (cnt[b] >= KEEPM) prefix = cand;
    }
    bool kp[3]; int c2 = 0;
    #pragma unroll
    for (int q = 0; q < 3; q++) { kp[q] = (k[q] >= prefix); c2 += kp[q] ? 1 : 0; }
    scan[t] = c2;
    __syncthreads();
    for (int off = 1; off < 1024; off <<= 1) {
        int v = (t >= off) ? scan[t - off] : 0;
        __syncthreads();
        scan[t] += v;
        __syncthreads();
    }
    int pos = scan[t] - c2;
    #pragma unroll
    for (int q = 0; q < 3; q++)
        if (kp[q]) g_keep[pos++] = 1024 + t*3 + q;
}

// ---------------- gather pruned KV ----------------
__global__ void gather_kv(const float* __restrict__ pk, const float* __restrict__ pv,
                          float* __restrict__ nk, float* __restrict__ nv) {
    const int rowid = blockIdx.x * 16 + (threadIdx.x >> 4);
    const int d4 = (threadIdx.x & 15) * 4;
    const int h = rowid >> 12;
    const int r = rowid & 4095;
    const int idx = (r < 1024) ? r : ((r < 3072) ? g_keep[r - 1024] : r + 1024);
    const float* ks; const float* vs;
    if (idx < TPAST) {
        ks = pk + (size_t)(h * TPAST + idx) * 64;
        vs = pv + (size_t)(h * TPAST + idx) * 64;
    } else {
        ks = g_kn + (size_t)((h << 10) + (idx - TPAST)) * 64;
        vs = g_vn + (size_t)((h << 10) + (idx - TPAST)) * 64;
    }
    *(float4*)(nk + (size_t)rowid * 64 + d4) = *(const float4*)(ks + d4);
    *(float4*)(nv + (size_t)rowid * 64 + d4) = *(const float4*)(vs + d4);
}

// ---------------- launch ----------------
extern "C" void kernel_launch(void* const* d_in, const int* in_sizes, int n_in,
                              void* d_out, int out_size) {
    const float* x      = (const float*)d_in[0];
    const float* past_k = (const float*)d_in[1];
    const float* past_v = (const float*)d_in[2];
    const float* qkv_w  = (const float*)d_in[3];
    const float* qkv_b  = (const float*)d_in[4];
    const float* proj_w = (const float*)d_in[5];
    const float* proj_b = (const float*)d_in[6];

    float* out = (float*)d_out;
    float* nk  = out + (size_t)Nq * DIMc;
    float* nv  = nk + (size_t)Hh * 4096 * 64;

    __half *kb, *vtb, *x16, *w16, *pw16, *o16;
    cudaGetSymbolAddress((void**)&kb,   g_kb);
    cudaGetSymbolAddress((void**)&vtb,  g_vtb);
    cudaGetSymbolAddress((void**)&x16,  g_x16);
    cudaGetSymbolAddress((void**)&w16,  g_w16);
    cudaGetSymbolAddress((void**)&pw16, g_pw16);
    cudaGetSymbolAddress((void**)&o16,  g_o16);

    // input conversions (independent)
    conv_f2h<<<1024, 256>>>(x, x16);                          // x -> f16
    conv_f2h<<<2048, 256>>>(qkv_w + (size_t)1024*1024, w16);  // k,v weights
    conv_f2h<<<1024, 256>>>(proj_w, pw16);                    // proj weights

    gemm_q<<<dim3(16, 16), 256>>>(x, qkv_w, qkv_b);           // fp32 q
    gemm_h16<<<dim3(32, 8), 256>>>(x16, w16, qkv_b + 1024, nullptr, 1); // f16 k,v

    conv_k<<<dim3(40, 16), 256>>>(past_k);
    conv_vt<<<dim3(80, 16), 256>>>(past_v);

    compute_m1<<<64, 256>>>();
    compute_m2<<<1, 64>>>();
    scores1<<<dim3(12, 16), 256>>>(past_k);
    scores2<<<3, 1024>>>();
    select_topk<<<1, 1024>>>();
    gather_kv<<<4096, 256>>>(past_k, past_v, nk, nv);

    attn_mma<<<dim3(8, 16), 256>>>(kb, vtb);
    conv_o<<<1024, 256>>>();
    gemm_h16<<<dim3(16, 8), 256>>>(o16, pw16, proj_b, out, 0);
}

// round 10
// speedup vs baseline: 3.5315x; 1.3008x over previous
#include <cuda_runtime.h>
#include <cuda_bf16.h>
#include <cuda_fp16.h>
#include <cstdint>

#define Hh    16
#define Dd    64
#define Nq    1024
#define TPAST 4096
#define TTOT  5120
#define DIMc  1024
#define MID   3072
#define KEEPM 2048
#define SCALE 0.125f

#define WSTR 72    // K rows: 144 B
#define VSTR 136   // V^T rows: 272 B

// ---------------- device scratch ----------------
__device__ float g_q [Hh*Nq*Dd];
__device__ float g_kn[Hh*Nq*Dd];
__device__ float g_vn[Hh*Nq*Dd];
__device__ float g_o [Nq*DIMc];
__device__ float g_scores[MID];
__device__ float g_m[Dd];
__device__ float g_xp[16*1024];
__device__ float g_xw[1024];
__device__ float g_mm[1024];
__device__ float g_sp[16*3072];
__device__ int   g_keep[KEEPM];
__device__ __half g_kb  [Hh*TTOT*Dd];   // K f16 [h][tok][d]
__device__ __half g_vtb [Hh*Dd*TTOT];   // V^T f16 [h][d][tok]
__device__ __half g_x16 [Nq*DIMc];      // x in f16
__device__ __half g_w16 [3072*DIMc];    // full qkv weight rows in f16
__device__ __half g_pw16[DIMc*DIMc];    // proj_w in f16
__device__ __half g_o16 [Nq*DIMc];      // attn out in f16

// ---------------- helpers ----------------
__device__ __forceinline__ void mma_f16(float* d, const uint32_t* a, uint32_t b0, uint32_t b1) {
    asm volatile("mma.sync.aligned.m16n8k16.row.col.f32.f16.f16.f32 "
        "{%0,%1,%2,%3}, {%4,%5,%6,%7}, {%8,%9}, {%0,%1,%2,%3};"
        : "+f"(d[0]), "+f"(d[1]), "+f"(d[2]), "+f"(d[3])
        : "r"(a[0]), "r"(a[1]), "r"(a[2]), "r"(a[3]), "r"(b0), "r"(b1));
}
__device__ __forceinline__ uint32_t expack(float x, float y) {
    __half2 p = __floats2half2_rn(__expf(x), __expf(y));
    return *reinterpret_cast<uint32_t*>(&p);
}
__device__ __forceinline__ uint32_t packh(float a, float b) {
    __half2 t = __floats2half2_rn(a, b);
    return *reinterpret_cast<uint32_t*>(&t);
}

// ---------------- generic fp32 -> f16 (count = grid*1024 elems) ----------
__global__ void conv_f2h(const float* __restrict__ s, __half* __restrict__ d) {
    int f = blockIdx.x * 256 + threadIdx.x;
    float4 v = *(const float4*)(s + (size_t)f * 4);
    *(uint2*)((char*)d + (size_t)f * 8) = make_uint2(packh(v.x, v.y), packh(v.z, v.w));
}
__global__ void conv_o() {
    int f = blockIdx.x * 256 + threadIdx.x;
    float4 v = *(const float4*)(g_o + (size_t)f * 4);
    *(uint2*)((char*)g_o16 + (size_t)f * 8) = make_uint2(packh(v.x, v.y), packh(v.z, v.w));
}

// ---------------- exact fp32 m-path: m from x and Wq directly ------------
// xw[c] = sum_n w(n) * x[n][c]
__global__ void xm1(const float* __restrict__ x) {
    const int c = blockIdx.x * 256 + threadIdx.x;   // grid.x = 4
    const int r0 = blockIdx.y * 64;                 // grid.y = 16
    float acc = 0.0f;
    for (int r = r0; r < r0 + 64; r++) {
        float w = (r < 5) ? 1.0f : (r < 1013 ? (1.0f / 16.0f) : (1.0f / 11.0f));
        acc += w * x[(size_t)r * 1024 + c];
    }
    g_xp[blockIdx.y * 1024 + c] = acc;
}
__global__ void xm2() {
    const int c = threadIdx.x;  // 1024
    float a = 0.0f;
    #pragma unroll
    for (int i = 0; i < 16; i++) a += g_xp[i * 1024 + c];
    g_xw[c] = a;
}
// mm[j] = Wq[j]·xw + 69*b[j]   (j = 0..1023)
__global__ void qm(const float* __restrict__ Wq, const float* __restrict__ qb) {
    __shared__ float red[256];
    __shared__ float xw[1024];
    const int t = threadIdx.x;
    for (int i = t; i < 1024; i += 256) xw[i] = g_xw[i];
    __syncthreads();
    const int jl = t >> 4, part = t & 15;
    const int j = blockIdx.x * 16 + jl;             // grid = 64
    const float* wr = Wq + (size_t)j * 1024 + part * 64;
    const float* xp = &xw[part * 64];
    float acc = 0.0f;
    #pragma unroll
    for (int cc = 0; cc < 64; cc += 4) {
        float4 v = *(const float4*)(wr + cc);
        acc += v.x * xp[cc] + v.y * xp[cc+1] + v.z * xp[cc+2] + v.w * xp[cc+3];
    }
    red[t] = acc;
    __syncthreads();
    if (part == 0) {
        float s = 0.0f;
        #pragma unroll
        for (int p = 0; p < 16; p++) s += red[jl * 16 + p];
        g_mm[j] = s + 69.0f * qb[j];
    }
}
__global__ void mfin() {
    const int d = threadIdx.x;  // 64
    float a = 0.0f;
    #pragma unroll
    for (int h = 0; h < 16; h++) a += g_mm[h * 64 + d];
    g_m[d] = a * (1.0f / (69.0f * 16.0f));
}

// ---------------- f16 tensor-core GEMM: C[n][j] = A[n]·B[j] + bias -------
// mode 0: linear C (stride 1024). mode 1: scatter all qkv cols to g_q/g_kn/g_vn.
__global__ void __launch_bounds__(256) gemm_h16(
    const __half* __restrict__ A, const __half* __restrict__ B,
    const float* __restrict__ bias, float* __restrict__ C, int mode)
{
    __shared__ __half As[128 * 72];
    __shared__ __half Bs[64 * 72];
    const int t = threadIdx.x, lane = t & 31, w = t >> 5;
    const int j0 = blockIdx.x * 64, n0 = blockIdx.y * 128;
    const int g = lane >> 2, i = lane & 3;
    float acc[8][4] = {};
    const uint4* Ag = (const uint4*)(A + (size_t)n0 * 1024);
    const uint4* Bg = (const uint4*)(B + (size_t)j0 * 1024);

    uint4 pa[4], pb[2];
    #pragma unroll
    for (int q = 0; q < 4; q++) { int f = q*256+t; pa[q] = Ag[(size_t)(f>>3)*128 + (f&7)]; }
    #pragma unroll
    for (int q = 0; q < 2; q++) { int f = q*256+t; pb[q] = Bg[(size_t)(f>>3)*128 + (f&7)]; }

    for (int c = 0; c < 16; c++) {
        __syncthreads();
        #pragma unroll
        for (int q = 0; q < 4; q++) { int f = q*256+t; *(uint4*)((char*)As + (f>>3)*144 + (f&7)*16) = pa[q]; }
        #pragma unroll
        for (int q = 0; q < 2; q++) { int f = q*256+t; *(uint4*)((char*)Bs + (f>>3)*144 + (f&7)*16) = pb[q]; }
        __syncthreads();
        if (c < 15) {
            #pragma unroll
            for (int q = 0; q < 4; q++) { int f = q*256+t; pa[q] = Ag[(size_t)(f>>3)*128 + (c+1)*8 + (f&7)]; }
            #pragma unroll
            for (int q = 0; q < 2; q++) { int f = q*256+t; pb[q] = Bg[(size_t)(f>>3)*128 + (c+1)*8 + (f&7)]; }
        }
        const uint32_t* Aw = (const uint32_t*)As;
        #pragma unroll
        for (int ks = 0; ks < 4; ks++) {
            uint32_t a[4];
            a[0] = Aw[(16*w + g)     * 36 + ks*8 + i];
            a[1] = Aw[(16*w + g + 8) * 36 + ks*8 + i];
            a[2] = Aw[(16*w + g)     * 36 + ks*8 + 4 + i];
            a[3] = Aw[(16*w + g + 8) * 36 + ks*8 + 4 + i];
            #pragma unroll
            for (int nb = 0; nb < 8; nb++) {
                const char* br = (const char*)Bs + (nb*8 + g)*144 + i*4 + ks*32;
                uint32_t b0 = *(const uint32_t*)br;
                uint32_t b1 = *(const uint32_t*)(br + 16);
                mma_f16(acc[nb], a, b0, b1);
            }
        }
    }
    const int r0 = n0 + 16*w + g;
    #pragma unroll
    for (int nb = 0; nb < 8; nb++) {
        int col = j0 + nb*8 + 2*i;
        float2 bv = *(const float2*)(bias + col);
        float2 w0 = make_float2(acc[nb][0] + bv.x, acc[nb][1] + bv.y);
        float2 w1 = make_float2(acc[nb][2] + bv.x, acc[nb][3] + bv.y);
        if (mode == 0) {
            *(float2*)(C + (size_t)r0 * 1024 + col)       = w0;
            *(float2*)(C + (size_t)(r0 + 8) * 1024 + col) = w1;
        } else {
            int sec = col >> 10;
            float* dst = (sec == 0) ? g_q : (sec == 1) ? g_kn : g_vn;
            int h = (col >> 6) & 15, d = col & 63;
            *(float2*)(dst + (size_t)((h << 10) + r0) * 64 + d)     = w0;
            *(float2*)(dst + (size_t)((h << 10) + r0 + 8) * 64 + d) = w1;
        }
    }
}

// ---------------- K -> f16 [h][tok][d] ----------------
__global__ void conv_k(const float* __restrict__ pk) {
    const int h = blockIdx.y, t0 = blockIdx.x * 128;
    const float* src = (t0 < TPAST) ? pk + ((size_t)h * TPAST + t0) * 64
                                    : g_kn + ((size_t)(h << 10) + (t0 - TPAST)) * 64;
    uint32_t* dst = reinterpret_cast<uint32_t*>(g_kb + ((size_t)h * TTOT + t0) * 64);
    const int t = threadIdx.x;
    #pragma unroll
    for (int q = 0; q < 8; q++) {
        int f = q * 256 + t;
        float4 v = *(const float4*)(src + (size_t)f * 4);
        dst[2*f]   = packh(v.x, v.y);
        dst[2*f+1] = packh(v.z, v.w);
    }
}

// ---------------- V -> f16 transposed [h][d][tok] ----------------
__global__ void conv_vt(const float* __restrict__ pv) {
    __shared__ float ts[64][65];
    const int h = blockIdx.y, t0 = blockIdx.x * 64;
    const float* src = (t0 < TPAST) ? pv + ((size_t)h * TPAST + t0) * 64
                                    : g_vn + ((size_t)(h << 10) + (t0 - TPAST)) * 64;
    const int t = threadIdx.x;
    #pragma unroll
    for (int q = 0; q < 4; q++) {
        int f = q * 256 + t;
        int tok = f >> 4, d4 = (f & 15) * 4;
        float4 v = *(const float4*)(src + (size_t)tok * 64 + d4);
        ts[tok][d4+0] = v.x; ts[tok][d4+1] = v.y; ts[tok][d4+2] = v.z; ts[tok][d4+3] = v.w;
    }
    __syncthreads();
    const int d = t >> 2, c0 = (t & 3) * 16;
    uint32_t* orow = reinterpret_cast<uint32_t*>(g_vtb + ((size_t)h * 64 + d) * TTOT + t0);
    #pragma unroll
    for (int k = 0; k < 8; k++) {
        int tok = c0 + 2 * k;
        orow[c0/2 + k] = packh(ts[tok][d], ts[tok+1][d]);
    }
}

// ---------------- attention: mma.sync flash kernel ----------
__global__ void __launch_bounds__(256, 1)
attn_mma(const __half* __restrict__ kb, const __half* __restrict__ vtb) {
    __shared__ __half Ks[128 * WSTR];
    __shared__ __half VTs[72 * VSTR];
    const int t = threadIdx.x, lane = t & 31, w = t >> 5;
    const int h = blockIdx.y, n0 = blockIdx.x * 128;
    const int g = lane >> 2, i = lane & 3;

    for (int f = t; f < 8 * 128; f += 256) {
        int r = f >> 7, c = f & 127;
        VTs[(64 + r) * VSTR + c] = (r == 0) ? __float2half(1.0f) : __float2half(0.0f);
    }

    uint32_t qa[4][4];
    {
        const float* qb = g_q + (size_t)((h << 10) + n0 + 16 * w) * 64;
        #pragma unroll
        for (int ks = 0; ks < 4; ks++) {
            float2 x0 = *(const float2*)(qb + g * 64 + 16 * ks + 2 * i);
            float2 x1 = *(const float2*)(qb + g * 64 + 16 * ks + 8 + 2 * i);
            float2 x2 = *(const float2*)(qb + (g + 8) * 64 + 16 * ks + 2 * i);
            float2 x3 = *(const float2*)(qb + (g + 8) * 64 + 16 * ks + 8 + 2 * i);
            qa[ks][0] = packh(x0.x * SCALE, x0.y * SCALE);
            qa[ks][1] = packh(x2.x * SCALE, x2.y * SCALE);
            qa[ks][2] = packh(x1.x * SCALE, x1.y * SCALE);
            qa[ks][3] = packh(x3.x * SCALE, x3.y * SCALE);
        }
    }

    const __half* kbh = kb + (size_t)h * TTOT * 64;
    const __half* vth = vtb + (size_t)h * 64 * TTOT;

    float o[9][4];
    #pragma unroll
    for (int nd = 0; nd < 9; nd++)
        #pragma unroll
        for (int c = 0; c < 4; c++) o[nd][c] = 0.0f;

    uint4 pk[4], pv[4];
    {
        const uint4* s = (const uint4*)kbh;
        #pragma unroll
        for (int q = 0; q < 4; q++) pk[q] = s[q * 256 + t];
        #pragma unroll
        for (int q = 0; q < 4; q++) {
            int f = q * 256 + t, d = f >> 4, c = f & 15;
            pv[q] = *(const uint4*)(vth + (size_t)d * TTOT + c * 8);
        }
    }

    for (int kt = 0; kt < 40; kt++) {
        __syncthreads();
        #pragma unroll
        for (int q = 0; q < 4; q++) {
            int f = q * 256 + t, tok = f >> 3, dc = f & 7;
            *(uint4*)((char*)Ks + tok * 144 + dc * 16) = pk[q];
        }
        #pragma unroll
        for (int q = 0; q < 4; q++) {
            int f = q * 256 + t, d = f >> 4, c = f & 15;
            *(uint4*)((char*)VTs + d * 272 + c * 16) = pv[q];
        }
        __syncthreads();
        if (kt < 39) {
            const uint4* s = (const uint4*)(kbh + (size_t)(kt + 1) * 128 * 64);
            #pragma unroll
            for (int q = 0; q < 4; q++) pk[q] = s[q * 256 + t];
            #pragma unroll
            for (int q = 0; q < 4; q++) {
                int f = q * 256 + t, d = f >> 4, c = f & 15;
                pv[q] = *(const uint4*)(vth + (size_t)d * TTOT + (kt + 1) * 128 + c * 8);
            }
        }

        float s[16][4];
        #pragma unroll
        for (int nb = 0; nb < 16; nb++) {
            s[nb][0] = s[nb][1] = s[nb][2] = s[nb][3] = 0.0f;
            const char* kr = (const char*)Ks + (nb * 8 + g) * 144 + i * 4;
            #pragma unroll
            for (int ks = 0; ks < 4; ks++) {
                uint32_t b0 = *(const uint32_t*)(kr + ks * 32);
                uint32_t b1 = *(const uint32_t*)(kr + ks * 32 + 16);
                mma_f16(s[nb], qa[ks], b0, b1);
            }
        }
        #pragma unroll
        for (int ks = 0; ks < 8; ks++) {
            uint32_t pa[4];
            pa[0] = expack(s[2*ks][0],   s[2*ks][1]);
            pa[1] = expack(s[2*ks][2],   s[2*ks][3]);
            pa[2] = expack(s[2*ks+1][0], s[2*ks+1][1]);
            pa[3] = expack(s[2*ks+1][2], s[2*ks+1][3]);
            const char* vr = (const char*)VTs + g * 272 + i * 4 + ks * 32;
            #pragma unroll
            for (int nd = 0; nd < 9; nd++) {
                uint32_t b0 = *(const uint32_t*)(vr + nd * 8 * 272);
                uint32_t b1 = *(const uint32_t*)(vr + nd * 8 * 272 + 16);
                mma_f16(o[nd], pa, b0, b1);
            }
        }
    }

    float lpg  = __shfl_sync(0xffffffffu, o[8][0], lane & ~3);
    float lpg8 = __shfl_sync(0xffffffffu, o[8][2], lane & ~3);
    float invg = 1.0f / lpg, inv8 = 1.0f / lpg8;
    const int r0 = n0 + 16 * w + g;
    float* ob = g_o + (size_t)r0 * DIMc + (h << 6) + 2 * i;
    #pragma unroll
    for (int nd = 0; nd < 8; nd++) {
        float2 w0 = make_float2(o[nd][0] * invg, o[nd][1] * invg);
        float2 w1 = make_float2(o[nd][2] * inv8, o[nd][3] * inv8);
        *(float2*)(ob + nd * 8)            = w0;
        *(float2*)(ob + 8 * DIMc + nd * 8) = w1;
    }
}

// ---------------- scores: per-(head, pos) partials then reduce ----------
__global__ void scores1(const float* __restrict__ pk) {
    __shared__ float m[64];
    if (threadIdx.x < 64) m[threadIdx.x] = g_m[threadIdx.x];
    __syncthreads();
    const int p = blockIdx.x * 256 + threadIdx.x, h = blockIdx.y;
    const float* kr = pk + (size_t)(h * TPAST + 1024 + p) * 64;
    float acc = 0.0f;
    #pragma unroll
    for (int d = 0; d < 64; d += 4) {
        float4 v = *(const float4*)(kr + d);
        acc += m[d] * v.x + m[d+1] * v.y + m[d+2] * v.z + m[d+3] * v.w;
    }
    g_sp[h * 3072 + p] = acc;
}
__global__ void scores2() {
    const int p = blockIdx.x * 1024 + threadIdx.x;
    float a = 0.0f;
    #pragma unroll
    for (int h = 0; h < 16; h++) a += g_sp[h * 3072 + p];
    g_scores[p] = a * (1.0f / 16.0f);
}

// ---- exact top-2048 via 64-bit bitwise radix select (keys unique) ----
__device__ __forceinline__ unsigned long long score_key(float s, int p) {
    unsigned u = __float_as_uint(s);
    u = (u & 0x80000000u) ? ~u : (u | 0x80000000u);
    return ((unsigned long long)u << 32) | (unsigned)(0xFFFFFFFFu - p);
}

__global__ void select_topk() {
    __shared__ int cnt[64];
    __shared__ int scan[1024];
    const int t = threadIdx.x, lid = t & 31;
    unsigned long long k[3];
    #pragma unroll
    for (int q = 0; q < 3; q++) k[q] = score_key(g_scores[t*3+q], t*3+q);
    if (t < 64) cnt[t] = 0;
    __syncthreads();
    unsigned long long prefix = 0;
    for (int b = 63; b >= 0; b--) {
        unsigned long long cand = prefix | (1ULL << b);
        int c = (int)(k[0] >= cand) + (int)(k[1] >= cand) + (int)(k[2] >= cand);
        #pragma unroll
        for (int o = 16; o; o >>= 1) c += __shfl_xor_sync(0xffffffffu, c, o);
        if (lid == 0) atomicAdd(&cnt[b], c);
        __syncthreads();
        if (cnt[b] >= KEEPM) prefix = cand;
    }
    bool kp[3]; int c2 = 0;
    #pragma unroll
    for (int q = 0; q < 3; q++) { kp[q] = (k[q] >= prefix); c2 += kp[q] ? 1 : 0; }
    scan[t] = c2;
    __syncthreads();
    for (int off = 1; off < 1024; off <<= 1) {
        int v = (t >= off) ? scan[t - off] : 0;
        __syncthreads();
        scan[t] += v;
        __syncthreads();
    }
    int pos = scan[t] - c2;
    #pragma unroll
    for (int q = 0; q < 3; q++)
        if (kp[q]) g_keep[pos++] = 1024 + t*3 + q;
}

// ---------------- gather pruned KV ----------------
__global__ void gather_kv(const float* __restrict__ pk, const float* __restrict__ pv,
                          float* __restrict__ nk, float* __restrict__ nv) {
    const int rowid = blockIdx.x * 16 + (threadIdx.x >> 4);
    const int d4 = (threadIdx.x & 15) * 4;
    const int h = rowid >> 12;
    const int r = rowid & 4095;
    const int idx = (r < 1024) ? r : ((r < 3072) ? g_keep[r - 1024] : r + 1024);
    const float* ks; const float* vs;
    if (idx < TPAST) {
        ks = pk + (size_t)(h * TPAST + idx) * 64;
        vs = pv + (size_t)(h * TPAST + idx) * 64;
    } else {
        ks = g_kn + (size_t)((h << 10) + (idx - TPAST)) * 64;
        vs = g_vn + (size_t)((h << 10) + (idx - TPAST)) * 64;
    }
    *(float4*)(nk + (size_t)rowid * 64 + d4) = *(const float4*)(ks + d4);
    *(float4*)(nv + (size_t)rowid * 64 + d4) = *(const float4*)(vs + d4);
}

// ---------------- launch ----------------
extern "C" void kernel_launch(void* const* d_in, const int* in_sizes, int n_in,
                              void* d_out, int out_size) {
    const float* x      = (const float*)d_in[0];
    const float* past_k = (const float*)d_in[1];
    const float* past_v = (const float*)d_in[2];
    const float* qkv_w  = (const float*)d_in[3];
    const float* qkv_b  = (const float*)d_in[4];
    const float* proj_w = (const float*)d_in[5];
    const float* proj_b = (const float*)d_in[6];

    float* out = (float*)d_out;
    float* nk  = out + (size_t)Nq * DIMc;
    float* nv  = nk + (size_t)Hh * 4096 * 64;

    __half *kb, *vtb, *x16, *w16, *pw16, *o16;
    cudaGetSymbolAddress((void**)&kb,   g_kb);
    cudaGetSymbolAddress((void**)&vtb,  g_vtb);
    cudaGetSymbolAddress((void**)&x16,  g_x16);
    cudaGetSymbolAddress((void**)&w16,  g_w16);
    cudaGetSymbolAddress((void**)&pw16, g_pw16);
    cudaGetSymbolAddress((void**)&o16,  g_o16);

    // conversions + exact fp32 m-path (independent of the GEMMs)
    conv_f2h<<<1024, 256>>>(x, x16);
    conv_f2h<<<3072, 256>>>(qkv_w, w16);
    conv_f2h<<<1024, 256>>>(proj_w, pw16);
    xm1<<<dim3(4, 16), 256>>>(x);
    xm2<<<1, 1024>>>();
    qm<<<64, 256>>>(qkv_w, qkv_b);
    mfin<<<1, 64>>>();

    // full qkv via f16 tensor GEMM (scatter q/k/v)
    gemm_h16<<<dim3(48, 8), 256>>>(x16, w16, qkv_b, nullptr, 1);

    conv_k<<<dim3(40, 16), 256>>>(past_k);
    conv_vt<<<dim3(80, 16), 256>>>(past_v);

    scores1<<<dim3(12, 16), 256>>>(past_k);
    scores2<<<3, 1024>>>();
    select_topk<<<1, 1024>>>();
    gather_kv<<<4096, 256>>>(past_k, past_v, nk, nv);

    attn_mma<<<dim3(8, 16), 256>>>(kb, vtb);
    conv_o<<<1024, 256>>>();
    gemm_h16<<<dim3(16, 8), 256>>>(o16, pw16, proj_b, out, 0);
}

// round 11
// speedup vs baseline: 3.5961x; 1.0183x over previous
#include <cuda_runtime.h>
#include <cuda_bf16.h>
#include <cuda_fp16.h>
#include <cstdint>

#define Hh    16
#define Dd    64
#define Nq    1024
#define TPAST 4096
#define TTOT  5120
#define DIMc  1024
#define MID   3072
#define KEEPM 2048
#define SCALE 0.125f

#define KSB   18432            // K tile bytes (128 rows x 144B)
#define BUFB  38016            // K tile + V tile (72 x 272B)
#define ATTN_SMEM (4 * BUFB)   // 2 warp-groups x 2 buffers

// ---------------- device scratch ----------------
__device__ float g_q [Hh*Nq*Dd];
__device__ float g_kn[Hh*Nq*Dd];
__device__ float g_vn[Hh*Nq*Dd];
__device__ float g_o [Nq*DIMc];
__device__ float g_scores[MID];
__device__ float g_m[Dd];
__device__ float g_xp[64*1024];
__device__ float g_xw[1024];
__device__ float g_mm[1024];
__device__ float g_sp[16*3072];
__device__ int   g_keep[KEEPM];
__device__ __half g_kb  [Hh*TTOT*Dd];   // K f16 [h][tok][d]
__device__ __half g_vtb [Hh*Dd*TTOT];   // V^T f16 [h][d][tok]
__device__ __half g_x16 [Nq*DIMc];
__device__ __half g_w16 [3072*DIMc];
__device__ __half g_pw16[DIMc*DIMc];
__device__ __half g_o16 [Nq*DIMc];

// ---------------- helpers ----------------
__device__ __forceinline__ void mma_f16(float* d, const uint32_t* a, uint32_t b0, uint32_t b1) {
    asm volatile("mma.sync.aligned.m16n8k16.row.col.f32.f16.f16.f32 "
        "{%0,%1,%2,%3}, {%4,%5,%6,%7}, {%8,%9}, {%0,%1,%2,%3};"
        : "+f"(d[0]), "+f"(d[1]), "+f"(d[2]), "+f"(d[3])
        : "r"(a[0]), "r"(a[1]), "r"(a[2]), "r"(a[3]), "r"(b0), "r"(b1));
}
__device__ __forceinline__ uint32_t expack(float x, float y) {
    __half2 p = __floats2half2_rn(__expf(x), __expf(y));
    return *reinterpret_cast<uint32_t*>(&p);
}
__device__ __forceinline__ uint32_t packh(float a, float b) {
    __half2 t = __floats2half2_rn(a, b);
    return *reinterpret_cast<uint32_t*>(&t);
}
__device__ __forceinline__ void cp16(uint32_t dst, const void* src) {
    asm volatile("cp.async.cg.shared.global [%0], [%1], 16;" :: "r"(dst), "l"(src) : "memory");
}

// ---------------- generic fp32 -> f16 ----------
__global__ void conv_f2h(const float* __restrict__ s, __half* __restrict__ d) {
    int f = blockIdx.x * 256 + threadIdx.x;
    float4 v = *(const float4*)(s + (size_t)f * 4);
    *(uint2*)((char*)d + (size_t)f * 8) = make_uint2(packh(v.x, v.y), packh(v.z, v.w));
}
__global__ void conv_o() {
    int f = blockIdx.x * 256 + threadIdx.x;
    float4 v = *(const float4*)(g_o + (size_t)f * 4);
    *(uint2*)((char*)g_o16 + (size_t)f * 8) = make_uint2(packh(v.x, v.y), packh(v.z, v.w));
}

// ---------------- exact fp32 m-path ----------------
__global__ void xm1(const float* __restrict__ x) {
    const int c = blockIdx.x * 256 + threadIdx.x;   // grid.x = 4
    const int r0 = blockIdx.y * 16;                 // grid.y = 64
    float acc = 0.0f;
    for (int r = r0; r < r0 + 16; r++) {
        float w = (r < 5) ? 1.0f : (r < 1013 ? (1.0f / 16.0f) : (1.0f / 11.0f));
        acc += w * x[(size_t)r * 1024 + c];
    }
    g_xp[blockIdx.y * 1024 + c] = acc;
}
__global__ void xm2() {
    const int c = threadIdx.x;  // 1024
    float a = 0.0f;
    #pragma unroll
    for (int i = 0; i < 64; i++) a += g_xp[i * 1024 + c];
    g_xw[c] = a;
}
__global__ void qm(const float* __restrict__ Wq, const float* __restrict__ qb) {
    __shared__ float red[256];
    __shared__ float xw[1024];
    const int t = threadIdx.x;
    for (int i = t; i < 1024; i += 256) xw[i] = g_xw[i];
    __syncthreads();
    const int jl = t >> 4, part = t & 15;
    const int j = blockIdx.x * 16 + jl;             // grid = 64
    const float* wr = Wq + (size_t)j * 1024 + part * 64;
    const float* xp = &xw[part * 64];
    float acc = 0.0f;
    #pragma unroll
    for (int cc = 0; cc < 64; cc += 4) {
        float4 v = *(const float4*)(wr + cc);
        acc += v.x * xp[cc] + v.y * xp[cc+1] + v.z * xp[cc+2] + v.w * xp[cc+3];
    }
    red[t] = acc;
    __syncthreads();
    if (part == 0) {
        float s = 0.0f;
        #pragma unroll
        for (int p = 0; p < 16; p++) s += red[jl * 16 + p];
        g_mm[j] = s + 69.0f * qb[j];
    }
}
__global__ void mfin() {
    const int d = threadIdx.x;  // 64
    float a = 0.0f;
    #pragma unroll
    for (int h = 0; h < 16; h++) a += g_mm[h * 64 + d];
    g_m[d] = a * (1.0f / (69.0f * 16.0f));
}

// ---------------- f16 tensor-core GEMM ----------------
__global__ void __launch_bounds__(256) gemm_h16(
    const __half* __restrict__ A, const __half* __restrict__ B,
    const float* __restrict__ bias, float* __restrict__ C, int mode)
{
    __shared__ __half As[128 * 72];
    __shared__ __half Bs[64 * 72];
    const int t = threadIdx.x, lane = t & 31, w = t >> 5;
    const int j0 = blockIdx.x * 64, n0 = blockIdx.y * 128;
    const int g = lane >> 2, i = lane & 3;
    float acc[8][4] = {};
    const uint4* Ag = (const uint4*)(A + (size_t)n0 * 1024);
    const uint4* Bg = (const uint4*)(B + (size_t)j0 * 1024);

    uint4 pa[4], pb[2];
    #pragma unroll
    for (int q = 0; q < 4; q++) { int f = q*256+t; pa[q] = Ag[(size_t)(f>>3)*128 + (f&7)]; }
    #pragma unroll
    for (int q = 0; q < 2; q++) { int f = q*256+t; pb[q] = Bg[(size_t)(f>>3)*128 + (f&7)]; }

    for (int c = 0; c < 16; c++) {
        __syncthreads();
        #pragma unroll
        for (int q = 0; q < 4; q++) { int f = q*256+t; *(uint4*)((char*)As + (f>>3)*144 + (f&7)*16) = pa[q]; }
        #pragma unroll
        for (int q = 0; q < 2; q++) { int f = q*256+t; *(uint4*)((char*)Bs + (f>>3)*144 + (f&7)*16) = pb[q]; }
        __syncthreads();
        if (c < 15) {
            #pragma unroll
            for (int q = 0; q < 4; q++) { int f = q*256+t; pa[q] = Ag[(size_t)(f>>3)*128 + (c+1)*8 + (f&7)]; }
            #pragma unroll
            for (int q = 0; q < 2; q++) { int f = q*256+t; pb[q] = Bg[(size_t)(f>>3)*128 + (c+1)*8 + (f&7)]; }
        }
        const uint32_t* Aw = (const uint32_t*)As;
        #pragma unroll
        for (int ks = 0; ks < 4; ks++) {
            uint32_t a[4];
            a[0] = Aw[(16*w + g)     * 36 + ks*8 + i];
            a[1] = Aw[(16*w + g + 8) * 36 + ks*8 + i];
            a[2] = Aw[(16*w + g)     * 36 + ks*8 + 4 + i];
            a[3] = Aw[(16*w + g + 8) * 36 + ks*8 + 4 + i];
            #pragma unroll
            for (int nb = 0; nb < 8; nb++) {
                const char* br = (const char*)Bs + (nb*8 + g)*144 + i*4 + ks*32;
                uint32_t b0 = *(const uint32_t*)br;
                uint32_t b1 = *(const uint32_t*)(br + 16);
                mma_f16(acc[nb], a, b0, b1);
            }
        }
    }
    const int r0 = n0 + 16*w + g;
    #pragma unroll
    for (int nb = 0; nb < 8; nb++) {
        int col = j0 + nb*8 + 2*i;
        float2 bv = *(const float2*)(bias + col);
        float2 w0 = make_float2(acc[nb][0] + bv.x, acc[nb][1] + bv.y);
        float2 w1 = make_float2(acc[nb][2] + bv.x, acc[nb][3] + bv.y);
        if (mode == 0) {
            *(float2*)(C + (size_t)r0 * 1024 + col)       = w0;
            *(float2*)(C + (size_t)(r0 + 8) * 1024 + col) = w1;
        } else {
            int sec = col >> 10;
            float* dst = (sec == 0) ? g_q : (sec == 1) ? g_kn : g_vn;
            int h = (col >> 6) & 15, d = col & 63;
            *(float2*)(dst + (size_t)((h << 10) + r0) * 64 + d)     = w0;
            *(float2*)(dst + (size_t)((h << 10) + r0 + 8) * 64 + d) = w1;
        }
    }
}

// ---------------- K -> f16 [h][tok][d] ----------------
__global__ void conv_k(const float* __restrict__ pk) {
    const int h = blockIdx.y, t0 = blockIdx.x * 128;
    const float* src = (t0 < TPAST) ? pk + ((size_t)h * TPAST + t0) * 64
                                    : g_kn + ((size_t)(h << 10) + (t0 - TPAST)) * 64;
    uint32_t* dst = reinterpret_cast<uint32_t*>(g_kb + ((size_t)h * TTOT + t0) * 64);
    const int t = threadIdx.x;
    #pragma unroll
    for (int q = 0; q < 8; q++) {
        int f = q * 256 + t;
        float4 v = *(const float4*)(src + (size_t)f * 4);
        dst[2*f]   = packh(v.x, v.y);
        dst[2*f+1] = packh(v.z, v.w);
    }
}

// ---------------- V -> f16 transposed [h][d][tok] ----------------
__global__ void conv_vt(const float* __restrict__ pv) {
    __shared__ float ts[64][65];
    const int h = blockIdx.y, t0 = blockIdx.x * 64;
    const float* src = (t0 < TPAST) ? pv + ((size_t)h * TPAST + t0) * 64
                                    : g_vn + ((size_t)(h << 10) + (t0 - TPAST)) * 64;
    const int t = threadIdx.x;
    #pragma unroll
    for (int q = 0; q < 4; q++) {
        int f = q * 256 + t;
        int tok = f >> 4, d4 = (f & 15) * 4;
        float4 v = *(const float4*)(src + (size_t)tok * 64 + d4);
        ts[tok][d4+0] = v.x; ts[tok][d4+1] = v.y; ts[tok][d4+2] = v.z; ts[tok][d4+3] = v.w;
    }
    __syncthreads();
    const int d = t >> 2, c0 = (t & 3) * 16;
    uint32_t* orow = reinterpret_cast<uint32_t*>(g_vtb + ((size_t)h * 64 + d) * TTOT + t0);
    #pragma unroll
    for (int k = 0; k < 8; k++) {
        int tok = c0 + 2 * k;
        orow[c0/2 + k] = packh(ts[tok][d], ts[tok+1][d]);
    }
}

// ---------------- attention: 512-thread dual-warp-group flash ------------
// grid (8,16). warps 0-7 = wg0 (even KV tiles), 8-15 = wg1 (odd tiles).
// Each wg: double-buffered cp.async staging, private named barrier.
__global__ void __launch_bounds__(512, 1)
attn_mma(const __half* __restrict__ kb, const __half* __restrict__ vtb) {
    extern __shared__ char sm[];
    const int t = threadIdx.x, lane = t & 31, w = t >> 5;
    const int wg = w >> 3, wl = w & 7, tl = t & 255;
    const int h = blockIdx.y, n0 = blockIdx.x * 128;
    const int g = lane >> 2, i = lane & 3;
    const uint32_t smb = (uint32_t)__cvta_generic_to_shared(sm);
    const int base = wg * 2 * BUFB;
    const int barid = 1 + wg;

    // ones rows (d=64 ones, 65..71 zero) in both V buffers of this wg
    #pragma unroll
    for (int bb = 0; bb < 2; bb++) {
        char* vt = sm + base + bb * BUFB + KSB;
        for (int f = tl; f < 1024; f += 256) {
            int r = f >> 7, c = f & 127;
            *(__half*)(vt + (64 + r) * 272 + c * 2) =
                (r == 0) ? __float2half(1.0f) : __float2half(0.0f);
        }
    }

    // Q fragments (f16, pre-scaled) — warp rows 16*wl (same for both wgs)
    uint32_t qa[4][4];
    {
        const float* qb = g_q + (size_t)((h << 10) + n0 + 16 * wl) * 64;
        #pragma unroll
        for (int ks = 0; ks < 4; ks++) {
            float2 x0 = *(const float2*)(qb + g * 64 + 16 * ks + 2 * i);
            float2 x1 = *(const float2*)(qb + g * 64 + 16 * ks + 8 + 2 * i);
            float2 x2 = *(const float2*)(qb + (g + 8) * 64 + 16 * ks + 2 * i);
            float2 x3 = *(const float2*)(qb + (g + 8) * 64 + 16 * ks + 8 + 2 * i);
            qa[ks][0] = packh(x0.x * SCALE, x0.y * SCALE);
            qa[ks][1] = packh(x2.x * SCALE, x2.y * SCALE);
            qa[ks][2] = packh(x1.x * SCALE, x1.y * SCALE);
            qa[ks][3] = packh(x3.x * SCALE, x3.y * SCALE);
        }
    }

    const char* kbh = (const char*)(kb + (size_t)h * TTOT * 64);
    const char* vth = (const char*)(vtb + (size_t)h * 64 * TTOT);

    float o[9][4];
    #pragma unroll
    for (int nd = 0; nd < 9; nd++)
        #pragma unroll
        for (int c = 0; c < 4; c++) o[nd][c] = 0.0f;

    // stage tile kt into buffer bi of this wg
    auto stage = [&](int kt, int bi) {
        const char* ks = kbh + (size_t)kt * 16384;
        uint32_t kd = smb + base + bi * BUFB;
        #pragma unroll
        for (int q = 0; q < 4; q++) {
            int f = q * 256 + tl, tok = f >> 3, dc = f & 7;
            cp16(kd + tok * 144 + dc * 16, ks + tok * 128 + dc * 16);
        }
        uint32_t vd = kd + KSB;
        #pragma unroll
        for (int q = 0; q < 4; q++) {
            int f = q * 256 + tl, dd = f >> 4, c = f & 15;
            cp16(vd + dd * 272 + c * 16, vth + (size_t)dd * (TTOT * 2) + kt * 256 + c * 16);
        }
        asm volatile("cp.async.commit_group;" ::: "memory");
    };

    stage(wg, 0);
    for (int step = 0; step < 20; step++) {
        asm volatile("cp.async.wait_group 0;" ::: "memory");
        asm volatile("bar.sync %0, 256;" :: "r"(barid) : "memory");
        if (step < 19) stage(2 * (step + 1) + wg, (step + 1) & 1);
        const char* Ksb = sm + base + (step & 1) * BUFB;
        const char* VTb = Ksb + KSB;
        #pragma unroll
        for (int half = 0; half < 2; half++) {
            float s[8][4];
            #pragma unroll
            for (int nb = 0; nb < 8; nb++) {
                s[nb][0] = s[nb][1] = s[nb][2] = s[nb][3] = 0.0f;
                const char* kr = Ksb + ((half * 8 + nb) * 8 + g) * 144 + i * 4;
                #pragma unroll
                for (int ks = 0; ks < 4; ks++) {
                    uint32_t b0 = *(const uint32_t*)(kr + ks * 32);
                    uint32_t b1 = *(const uint32_t*)(kr + ks * 32 + 16);
                    mma_f16(s[nb], qa[ks], b0, b1);
                }
            }
            #pragma unroll
            for (int ks = 0; ks < 4; ks++) {
                uint32_t pa[4];
                pa[0] = expack(s[2*ks][0],   s[2*ks][1]);
                pa[1] = expack(s[2*ks][2],   s[2*ks][3]);
                pa[2] = expack(s[2*ks+1][0], s[2*ks+1][1]);
                pa[3] = expack(s[2*ks+1][2], s[2*ks+1][3]);
                const char* vr = VTb + g * 272 + i * 4 + (half * 4 + ks) * 32;
                #pragma unroll
                for (int nd = 0; nd < 9; nd++) {
                    uint32_t b0 = *(const uint32_t*)(vr + nd * 8 * 272);
                    uint32_t b1 = *(const uint32_t*)(vr + nd * 8 * 272 + 16);
                    mma_f16(o[nd], pa, b0, b1);
                }
            }
        }
    }

    // merge wg1 partials into wg0, then epilogue
    __syncthreads();
    float* ms = (float*)sm;
    const int slot = (wl * 32 + lane) * 36;
    if (wg == 1) {
        #pragma unroll
        for (int nd = 0; nd < 9; nd++)
            #pragma unroll
            for (int c = 0; c < 4; c++) ms[slot + nd * 4 + c] = o[nd][c];
    }
    __syncthreads();
    if (wg == 0) {
        #pragma unroll
        for (int nd = 0; nd < 9; nd++)
            #pragma unroll
            for (int c = 0; c < 4; c++) o[nd][c] += ms[slot + nd * 4 + c];
        float lpg  = __shfl_sync(0xffffffffu, o[8][0], lane & ~3);
        float lpg8 = __shfl_sync(0xffffffffu, o[8][2], lane & ~3);
        float invg = 1.0f / lpg, inv8 = 1.0f / lpg8;
        const int r0 = n0 + 16 * wl + g;
        float* ob = g_o + (size_t)r0 * DIMc + (h << 6) + 2 * i;
        #pragma unroll
        for (int nd = 0; nd < 8; nd++) {
            float2 w0 = make_float2(o[nd][0] * invg, o[nd][1] * invg);
            float2 w1 = make_float2(o[nd][2] * inv8, o[nd][3] * inv8);
            *(float2*)(ob + nd * 8)            = w0;
            *(float2*)(ob + 8 * DIMc + nd * 8) = w1;
        }
    }
}

// ---------------- scores ----------------
__global__ void scores1(const float* __restrict__ pk) {
    __shared__ float m[64];
    if (threadIdx.x < 64) m[threadIdx.x] = g_m[threadIdx.x];
    __syncthreads();
    const int p = blockIdx.x * 256 + threadIdx.x, h = blockIdx.y;
    const float* kr = pk + (size_t)(h * TPAST + 1024 + p) * 64;
    float acc = 0.0f;
    #pragma unroll
    for (int d = 0; d < 64; d += 4) {
        float4 v = *(const float4*)(kr + d);
        acc += m[d] * v.x + m[d+1] * v.y + m[d+2] * v.z + m[d+3] * v.w;
    }
    g_sp[h * 3072 + p] = acc;
}
__global__ void scores2() {
    const int p = blockIdx.x * 1024 + threadIdx.x;
    float a = 0.0f;
    #pragma unroll
    for (int h = 0; h < 16; h++) a += g_sp[h * 3072 + p];
    g_scores[p] = a * (1.0f / 16.0f);
}

// ---- exact top-2048 via 64-bit bitwise radix select ----
__device__ __forceinline__ unsigned long long score_key(float s, int p) {
    unsigned u = __float_as_uint(s);
    u = (u & 0x80000000u) ? ~u : (u | 0x80000000u);
    return ((unsigned long long)u << 32) | (unsigned)(0xFFFFFFFFu - p);
}

__global__ void select_topk() {
    __shared__ int cnt[64];
    __shared__ int scan[1024];
    const int t = threadIdx.x, lid = t & 31;
    unsigned long long k[3];
    #pragma unroll
    for (int q = 0; q < 3; q++) k[q] = score_key(g_scores[t*3+q], t*3+q);
    if (t < 64) cnt[t] = 0;
    __syncthreads();
    unsigned long long prefix = 0;
    for (int b = 63; b >= 0; b--) {
        unsigned long long cand = prefix | (1ULL << b);
        int c = (int)(k[0] >= cand) + (int)(k[1] >= cand) + (int)(k[2] >= cand);
        #pragma unroll
        for (int o = 16; o; o >>= 1) c += __shfl_xor_sync(0xffffffffu, c, o);
        if (lid == 0) atomicAdd(&cnt[b], c);
        __syncthreads();
        if (cnt[b] >= KEEPM) prefix = cand;
    }
    bool kp[3]; int c2 = 0;
    #pragma unroll
    for (int q = 0; q < 3; q++) { kp[q] = (k[q] >= prefix); c2 += kp[q] ? 1 : 0; }
    scan[t] = c2;
    __syncthreads();
    for (int off = 1; off < 1024; off <<= 1) {
        int v = (t >= off) ? scan[t - off] : 0;
        __syncthreads();
        scan[t] += v;
        __syncthreads();
    }
    int pos = scan[t] - c2;
    #pragma unroll
    for (int q = 0; q < 3; q++)
        if (kp[q]) g_keep[pos++] = 1024 + t*3 + q;
}

// ---------------- gather pruned KV ----------------
__global__ void gather_kv(const float* __restrict__ pk, const float* __restrict__ pv,
                          float* __restrict__ nk, float* __restrict__ nv) {
    const int rowid = blockIdx.x * 16 + (threadIdx.x >> 4);
    const int d4 = (threadIdx.x & 15) * 4;
    const int h = rowid >> 12;
    const int r = rowid & 4095;
    const int idx = (r < 1024) ? r : ((r < 3072) ? g_keep[r - 1024] : r + 1024);
    const float* ks; const float* vs;
    if (idx < TPAST) {
        ks = pk + (size_t)(h * TPAST + idx) * 64;
        vs = pv + (size_t)(h * TPAST + idx) * 64;
    } else {
        ks = g_kn + (size_t)((h << 10) + (idx - TPAST)) * 64;
        vs = g_vn + (size_t)((h << 10) + (idx - TPAST)) * 64;
    }
    *(float4*)(nk + (size_t)rowid * 64 + d4) = *(const float4*)(ks + d4);
    *(float4*)(nv + (size_t)rowid * 64 + d4) = *(const float4*)(vs + d4);
}

// ---------------- launch ----------------
extern "C" void kernel_launch(void* const* d_in, const int* in_sizes, int n_in,
                              void* d_out, int out_size) {
    const float* x      = (const float*)d_in[0];
    const float* past_k = (const float*)d_in[1];
    const float* past_v = (const float*)d_in[2];
    const float* qkv_w  = (const float*)d_in[3];
    const float* qkv_b  = (const float*)d_in[4];
    const float* proj_w = (const float*)d_in[5];
    const float* proj_b = (const float*)d_in[6];

    float* out = (float*)d_out;
    float* nk  = out + (size_t)Nq * DIMc;
    float* nv  = nk + (size_t)Hh * 4096 * 64;

    __half *kb, *vtb, *x16, *w16, *pw16, *o16;
    cudaGetSymbolAddress((void**)&kb,   g_kb);
    cudaGetSymbolAddress((void**)&vtb,  g_vtb);
    cudaGetSymbolAddress((void**)&x16,  g_x16);
    cudaGetSymbolAddress((void**)&w16,  g_w16);
    cudaGetSymbolAddress((void**)&pw16, g_pw16);
    cudaGetSymbolAddress((void**)&o16,  g_o16);

    cudaFuncSetAttribute(attn_mma, cudaFuncAttributeMaxDynamicSharedMemorySize, ATTN_SMEM);

    // conversions + exact fp32 m-path
    conv_f2h<<<1024, 256>>>(x, x16);
    conv_f2h<<<3072, 256>>>(qkv_w, w16);
    conv_f2h<<<1024, 256>>>(proj_w, pw16);
    xm1<<<dim3(4, 64), 256>>>(x);
    xm2<<<1, 1024>>>();
    qm<<<64, 256>>>(qkv_w, qkv_b);
    mfin<<<1, 64>>>();

    // full qkv via f16 tensor GEMM (scatter q/k/v)
    gemm_h16<<<dim3(48, 8), 256>>>(x16, w16, qkv_b, nullptr, 1);

    conv_k<<<dim3(40, 16), 256>>>(past_k);
    conv_vt<<<dim3(80, 16), 256>>>(past_v);

    scores1<<<dim3(12, 16), 256>>>(past_k);
    scores2<<<3, 1024>>>();
    select_topk<<<1, 1024>>>();
    gather_kv<<<4096, 256>>>(past_k, past_v, nk, nv);

    attn_mma<<<dim3(8, 16), 512, ATTN_SMEM>>>(kb, vtb);
    conv_o<<<1024, 256>>>();
    gemm_h16<<<dim3(16, 8), 256>>>(o16, pw16, proj_b, out, 0);
}

// round 12
// speedup vs baseline: 4.0303x; 1.1207x over previous
#include <cuda_runtime.h>
#include <cuda_bf16.h>
#include <cuda_fp16.h>
#include <cstdint>

#define Hh    16
#define Dd    64
#define Nq    1024
#define TPAST 4096
#define TTOT  5120
#define DIMc  1024
#define MID   3072
#define KEEPM 2048
#define SCALE 0.125f

#define KSB   18432            // K tile bytes (128 rows x 144B)
#define BUFB  38016            // K tile + V tile (72 x 272B)
#define ATTN_SMEM (4 * BUFB)   // 2 warp-groups x 2 buffers

// ---------------- device scratch ----------------
__device__ float g_q [Hh*Nq*Dd];
__device__ float g_kn[Hh*Nq*Dd];
__device__ float g_vn[Hh*Nq*Dd];
__device__ float g_scores[MID];
__device__ float g_m[Dd];
__device__ float g_xp[64*1024];
__device__ float g_xw[1024];
__device__ float g_mm[1024];
__device__ float g_sp[16*3072];
__device__ int   g_keep[KEEPM];
__device__ __half g_kb  [Hh*TTOT*Dd];   // K f16 [h][tok][d]
__device__ __half g_vtb [Hh*Dd*TTOT];   // V^T f16 [h][d][tok]
__device__ __half g_x16 [Nq*DIMc];
__device__ __half g_w16 [3072*DIMc];
__device__ __half g_pw16[DIMc*DIMc];
__device__ __half g_o16 [Nq*DIMc];      // attn out, f16 (written by attn epilogue)

// ---------------- helpers ----------------
__device__ __forceinline__ void mma_f16(float* d, const uint32_t* a, uint32_t b0, uint32_t b1) {
    asm volatile("mma.sync.aligned.m16n8k16.row.col.f32.f16.f16.f32 "
        "{%0,%1,%2,%3}, {%4,%5,%6,%7}, {%8,%9}, {%0,%1,%2,%3};"
        : "+f"(d[0]), "+f"(d[1]), "+f"(d[2]), "+f"(d[3])
        : "r"(a[0]), "r"(a[1]), "r"(a[2]), "r"(a[3]), "r"(b0), "r"(b1));
}
__device__ __forceinline__ uint32_t expack(float x, float y) {
    __half2 p = __floats2half2_rn(__expf(x), __expf(y));
    return *reinterpret_cast<uint32_t*>(&p);
}
__device__ __forceinline__ uint32_t packh(float a, float b) {
    __half2 t = __floats2half2_rn(a, b);
    return *reinterpret_cast<uint32_t*>(&t);
}
__device__ __forceinline__ void cp16(uint32_t dst, const void* src) {
    asm volatile("cp.async.cg.shared.global [%0], [%1], 16;" :: "r"(dst), "l"(src) : "memory");
}
__device__ __forceinline__ void conv_range(const float* __restrict__ s, __half* __restrict__ d, int f) {
    float4 v = *(const float4*)(s + (size_t)f * 4);
    *(uint2*)((char*)d + (size_t)f * 8) = make_uint2(packh(v.x, v.y), packh(v.z, v.w));
}

// ---------------- stage1: all input conversions + xm1 --------------------
// grid 5376 x 256: [0,1024) x->x16 | [1024,4096) qkv_w->w16 |
// [4096,5120) proj_w->pw16 | [5120,5376) xm1
__global__ void stage1(const float* __restrict__ x, const float* __restrict__ qkv_w,
                       const float* __restrict__ proj_w) {
    const int b = blockIdx.x, t = threadIdx.x;
    if (b < 1024) {
        conv_range(x, g_x16, b * 256 + t);
    } else if (b < 4096) {
        conv_range(qkv_w, g_w16, (b - 1024) * 256 + t);
    } else if (b < 5120) {
        conv_range(proj_w, g_pw16, (b - 4096) * 256 + t);
    } else {
        const int q = b - 5120;              // 256 blocks: 4 c-blks x 64 r-blks
        const int c = (q & 3) * 256 + t;
        const int r0 = (q >> 2) * 16;
        float acc = 0.0f;
        for (int r = r0; r < r0 + 16; r++) {
            float w = (r < 5) ? 1.0f : (r < 1013 ? (1.0f / 16.0f) : (1.0f / 11.0f));
            acc += w * x[(size_t)r * 1024 + c];
        }
        g_xp[(q >> 2) * 1024 + c] = acc;
    }
}

// ---------------- exact fp32 m-path tail ----------------
__global__ void xm2() {
    const int c = threadIdx.x;  // 1024
    float a = 0.0f;
    #pragma unroll
    for (int i = 0; i < 64; i++) a += g_xp[i * 1024 + c];
    g_xw[c] = a;
}
__global__ void qm(const float* __restrict__ Wq, const float* __restrict__ qb) {
    __shared__ float red[256];
    __shared__ float xw[1024];
    const int t = threadIdx.x;
    for (int i = t; i < 1024; i += 256) xw[i] = g_xw[i];
    __syncthreads();
    const int jl = t >> 4, part = t & 15;
    const int j = blockIdx.x * 16 + jl;             // grid = 64
    const float* wr = Wq + (size_t)j * 1024 + part * 64;
    const float* xp = &xw[part * 64];
    float acc = 0.0f;
    #pragma unroll
    for (int cc = 0; cc < 64; cc += 4) {
        float4 v = *(const float4*)(wr + cc);
        acc += v.x * xp[cc] + v.y * xp[cc+1] + v.z * xp[cc+2] + v.w * xp[cc+3];
    }
    red[t] = acc;
    __syncthreads();
    if (part == 0) {
        float s = 0.0f;
        #pragma unroll
        for (int p = 0; p < 16; p++) s += red[jl * 16 + p];
        g_mm[j] = s + 69.0f * qb[j];
    }
}
__global__ void mfin() {
    const int d = threadIdx.x;  // 64
    float a = 0.0f;
    #pragma unroll
    for (int h = 0; h < 16; h++) a += g_mm[h * 64 + d];
    g_m[d] = a * (1.0f / (69.0f * 16.0f));
}

// ---------------- f16 tensor-core GEMM ----------------
__global__ void __launch_bounds__(256) gemm_h16(
    const __half* __restrict__ A, const __half* __restrict__ B,
    const float* __restrict__ bias, float* __restrict__ C, int mode)
{
    __shared__ __half As[128 * 72];
    __shared__ __half Bs[64 * 72];
    const int t = threadIdx.x, lane = t & 31, w = t >> 5;
    const int j0 = blockIdx.x * 64, n0 = blockIdx.y * 128;
    const int g = lane >> 2, i = lane & 3;
    float acc[8][4] = {};
    const uint4* Ag = (const uint4*)(A + (size_t)n0 * 1024);
    const uint4* Bg = (const uint4*)(B + (size_t)j0 * 1024);

    uint4 pa[4], pb[2];
    #pragma unroll
    for (int q = 0; q < 4; q++) { int f = q*256+t; pa[q] = Ag[(size_t)(f>>3)*128 + (f&7)]; }
    #pragma unroll
    for (int q = 0; q < 2; q++) { int f = q*256+t; pb[q] = Bg[(size_t)(f>>3)*128 + (f&7)]; }

    for (int c = 0; c < 16; c++) {
        __syncthreads();
        #pragma unroll
        for (int q = 0; q < 4; q++) { int f = q*256+t; *(uint4*)((char*)As + (f>>3)*144 + (f&7)*16) = pa[q]; }
        #pragma unroll
        for (int q = 0; q < 2; q++) { int f = q*256+t; *(uint4*)((char*)Bs + (f>>3)*144 + (f&7)*16) = pb[q]; }
        __syncthreads();
        if (c < 15) {
            #pragma unroll
            for (int q = 0; q < 4; q++) { int f = q*256+t; pa[q] = Ag[(size_t)(f>>3)*128 + (c+1)*8 + (f&7)]; }
            #pragma unroll
            for (int q = 0; q < 2; q++) { int f = q*256+t; pb[q] = Bg[(size_t)(f>>3)*128 + (c+1)*8 + (f&7)]; }
        }
        const uint32_t* Aw = (const uint32_t*)As;
        #pragma unroll
        for (int ks = 0; ks < 4; ks++) {
            uint32_t a[4];
            a[0] = Aw[(16*w + g)     * 36 + ks*8 + i];
            a[1] = Aw[(16*w + g + 8) * 36 + ks*8 + i];
            a[2] = Aw[(16*w + g)     * 36 + ks*8 + 4 + i];
            a[3] = Aw[(16*w + g + 8) * 36 + ks*8 + 4 + i];
            #pragma unroll
            for (int nb = 0; nb < 8; nb++) {
                const char* br = (const char*)Bs + (nb*8 + g)*144 + i*4 + ks*32;
                uint32_t b0 = *(const uint32_t*)br;
                uint32_t b1 = *(const uint32_t*)(br + 16);
                mma_f16(acc[nb], a, b0, b1);
            }
        }
    }
    const int r0 = n0 + 16*w + g;
    #pragma unroll
    for (int nb = 0; nb < 8; nb++) {
        int col = j0 + nb*8 + 2*i;
        float2 bv = *(const float2*)(bias + col);
        float2 w0 = make_float2(acc[nb][0] + bv.x, acc[nb][1] + bv.y);
        float2 w1 = make_float2(acc[nb][2] + bv.x, acc[nb][3] + bv.y);
        if (mode == 0) {
            *(float2*)(C + (size_t)r0 * 1024 + col)       = w0;
            *(float2*)(C + (size_t)(r0 + 8) * 1024 + col) = w1;
        } else {
            int sec = col >> 10;
            float* dst = (sec == 0) ? g_q : (sec == 1) ? g_kn : g_vn;
            int h = (col >> 6) & 15, d = col & 63;
            *(float2*)(dst + (size_t)((h << 10) + r0) * 64 + d)     = w0;
            *(float2*)(dst + (size_t)((h << 10) + r0 + 8) * 64 + d) = w1;
        }
    }
}

// ---------------- stagekv: conv_k + conv_vt + scores1 fused --------------
// grid (132,16): bx<40 conv_k | bx<120 conv_vt | bx<132 scores1
__global__ void stagekv(const float* __restrict__ pk, const float* __restrict__ pv) {
    __shared__ float ts[64][65];
    const int h = blockIdx.y, t = threadIdx.x;
    const int bx = blockIdx.x;
    if (bx < 40) {
        const int t0 = bx * 128;
        const float* src = (t0 < TPAST) ? pk + ((size_t)h * TPAST + t0) * 64
                                        : g_kn + ((size_t)(h << 10) + (t0 - TPAST)) * 64;
        uint32_t* dst = reinterpret_cast<uint32_t*>(g_kb + ((size_t)h * TTOT + t0) * 64);
        #pragma unroll
        for (int q = 0; q < 8; q++) {
            int f = q * 256 + t;
            float4 v = *(const float4*)(src + (size_t)f * 4);
            dst[2*f]   = packh(v.x, v.y);
            dst[2*f+1] = packh(v.z, v.w);
        }
    } else if (bx < 120) {
        const int t0 = (bx - 40) * 64;
        const float* src = (t0 < TPAST) ? pv + ((size_t)h * TPAST + t0) * 64
                                        : g_vn + ((size_t)(h << 10) + (t0 - TPAST)) * 64;
        #pragma unroll
        for (int q = 0; q < 4; q++) {
            int f = q * 256 + t;
            int tok = f >> 4, d4 = (f & 15) * 4;
            float4 v = *(const float4*)(src + (size_t)tok * 64 + d4);
            ts[tok][d4+0] = v.x; ts[tok][d4+1] = v.y; ts[tok][d4+2] = v.z; ts[tok][d4+3] = v.w;
        }
        __syncthreads();
        const int d = t >> 2, c0 = (t & 3) * 16;
        uint32_t* orow = reinterpret_cast<uint32_t*>(g_vtb + ((size_t)h * 64 + d) * TTOT + t0);
        #pragma unroll
        for (int k = 0; k < 8; k++) {
            int tok = c0 + 2 * k;
            orow[c0/2 + k] = packh(ts[tok][d], ts[tok+1][d]);
        }
    } else {
        float* m = &ts[0][0];
        if (t < 64) m[t] = g_m[t];
        __syncthreads();
        const int p = (bx - 120) * 256 + t;
        const float* kr = pk + (size_t)(h * TPAST + 1024 + p) * 64;
        float acc = 0.0f;
        #pragma unroll
        for (int d = 0; d < 64; d += 4) {
            float4 v = *(const float4*)(kr + d);
            acc += m[d] * v.x + m[d+1] * v.y + m[d+2] * v.z + m[d+3] * v.w;
        }
        g_sp[h * 3072 + p] = acc;
    }
}

// ---- scores head-reduce + exact top-2048 radix select (fused) ----
__device__ __forceinline__ unsigned long long score_key(float s, int p) {
    unsigned u = __float_as_uint(s);
    u = (u & 0x80000000u) ? ~u : (u | 0x80000000u);
    return ((unsigned long long)u << 32) | (unsigned)(0xFFFFFFFFu - p);
}

__global__ void select_topk() {
    __shared__ int cnt[64];
    __shared__ int scan[1024];
    const int t = threadIdx.x, lid = t & 31;
    unsigned long long k[3];
    #pragma unroll
    for (int q = 0; q < 3; q++) {
        int p = t * 3 + q;
        float a = 0.0f;
        #pragma unroll
        for (int h = 0; h < 16; h++) a += g_sp[h * 3072 + p];
        k[q] = score_key(a * (1.0f / 16.0f), p);
    }
    if (t < 64) cnt[t] = 0;
    __syncthreads();
    unsigned long long prefix = 0;
    for (int b = 63; b >= 0; b--) {
        unsigned long long cand = prefix | (1ULL << b);
        int c = (int)(k[0] >= cand) + (int)(k[1] >= cand) + (int)(k[2] >= cand);
        #pragma unroll
        for (int o = 16; o; o >>= 1) c += __shfl_xor_sync(0xffffffffu, c, o);
        if (lid == 0) atomicAdd(&cnt[b], c);
        __syncthreads();
        if (cnt[b] >= KEEPM) prefix = cand;
    }
    bool kp[3]; int c2 = 0;
    #pragma unroll
    for (int q = 0; q < 3; q++) { kp[q] = (k[q] >= prefix); c2 += kp[q] ? 1 : 0; }
    scan[t] = c2;
    __syncthreads();
    for (int off = 1; off < 1024; off <<= 1) {
        int v = (t >= off) ? scan[t - off] : 0;
        __syncthreads();
        scan[t] += v;
        __syncthreads();
    }
    int pos = scan[t] - c2;
    #pragma unroll
    for (int q = 0; q < 3; q++)
        if (kp[q]) g_keep[pos++] = 1024 + t * 3 + q;
}

// ---------------- attention + gather fused ----------------
// grid (8,24) x 512. by<16: attn (h=by). by>=16: gather role
// (64 CTAs, h = (by-16)*2 + (bx>>2), quarter rc = bx&3). Gather CTAs are
// AFTER all attn CTAs in linear order, so wave 1 is attn-first.
__global__ void __launch_bounds__(512, 1)
attn_mma(const __half* __restrict__ kb, const __half* __restrict__ vtb,
         const float* __restrict__ pk, const float* __restrict__ pv,
         float* __restrict__ nk, float* __restrict__ nv) {
    extern __shared__ char sm[];
    const int t = threadIdx.x, lane = t & 31, w = t >> 5;

    if (blockIdx.y >= 16) {      // ---- gather role ----
        const int h = (blockIdx.y - 16) * 2 + (blockIdx.x >> 2);
        const int rc = blockIdx.x & 3;
        const int d4 = (t & 15) * 4;
        const int rbase = rc * 1024 + (t >> 4);
        #pragma unroll 4
        for (int j = 0; j < 32; j++) {
            const int r = rbase + j * 32;
            const int idx = (r < 1024) ? r : ((r < 3072) ? g_keep[r - 1024] : r + 1024);
            const float* ks; const float* vs;
            if (idx < TPAST) {
                ks = pk + (size_t)(h * TPAST + idx) * 64;
                vs = pv + (size_t)(h * TPAST + idx) * 64;
            } else {
                ks = g_kn + (size_t)((h << 10) + (idx - TPAST)) * 64;
                vs = g_vn + (size_t)((h << 10) + (idx - TPAST)) * 64;
            }
            const size_t rowid = (size_t)(h << 12) + r;
            *(float4*)(nk + rowid * 64 + d4) = *(const float4*)(ks + d4);
            *(float4*)(nv + rowid * 64 + d4) = *(const float4*)(vs + d4);
        }
        return;
    }

    // ---- attention role ----
    const int wg = w >> 3, wl = w & 7, tl = t & 255;
    const int h = blockIdx.y, n0 = blockIdx.x * 128;
    const int g = lane >> 2, i = lane & 3;
    const uint32_t smb = (uint32_t)__cvta_generic_to_shared(sm);
    const int base = wg * 2 * BUFB;
    const int barid = 1 + wg;

    #pragma unroll
    for (int bb = 0; bb < 2; bb++) {
        char* vt = sm + base + bb * BUFB + KSB;
        for (int f = tl; f < 1024; f += 256) {
            int r = f >> 7, c = f & 127;
            *(__half*)(vt + (64 + r) * 272 + c * 2) =
                (r == 0) ? __float2half(1.0f) : __float2half(0.0f);
        }
    }

    uint32_t qa[4][4];
    {
        const float* qb = g_q + (size_t)((h << 10) + n0 + 16 * wl) * 64;
        #pragma unroll
        for (int ks = 0; ks < 4; ks++) {
            float2 x0 = *(const float2*)(qb + g * 64 + 16 * ks + 2 * i);
            float2 x1 = *(const float2*)(qb + g * 64 + 16 * ks + 8 + 2 * i);
            float2 x2 = *(const float2*)(qb + (g + 8) * 64 + 16 * ks + 2 * i);
            float2 x3 = *(const float2*)(qb + (g + 8) * 64 + 16 * ks + 8 + 2 * i);
            qa[ks][0] = packh(x0.x * SCALE, x0.y * SCALE);
            qa[ks][1] = packh(x2.x * SCALE, x2.y * SCALE);
            qa[ks][2] = packh(x1.x * SCALE, x1.y * SCALE);
            qa[ks][3] = packh(x3.x * SCALE, x3.y * SCALE);
        }
    }

    const char* kbh = (const char*)(kb + (size_t)h * TTOT * 64);
    const char* vth = (const char*)(vtb + (size_t)h * 64 * TTOT);

    float o[9][4];
    #pragma unroll
    for (int nd = 0; nd < 9; nd++)
        #pragma unroll
        for (int c = 0; c < 4; c++) o[nd][c] = 0.0f;

    auto stage = [&](int kt, int bi) {
        const char* ks = kbh + (size_t)kt * 16384;
        uint32_t kd = smb + base + bi * BUFB;
        #pragma unroll
        for (int q = 0; q < 4; q++) {
            int f = q * 256 + tl, tok = f >> 3, dc = f & 7;
            cp16(kd + tok * 144 + dc * 16, ks + tok * 128 + dc * 16);
        }
        uint32_t vd = kd + KSB;
        #pragma unroll
        for (int q = 0; q < 4; q++) {
            int f = q * 256 + tl, dd = f >> 4, c = f & 15;
            cp16(vd + dd * 272 + c * 16, vth + (size_t)dd * (TTOT * 2) + kt * 256 + c * 16);
        }
        asm volatile("cp.async.commit_group;" ::: "memory");
    };

    stage(wg, 0);
    for (int step = 0; step < 20; step++) {
        asm volatile("cp.async.wait_group 0;" ::: "memory");
        asm volatile("bar.sync %0, 256;" :: "r"(barid) : "memory");
        if (step < 19) stage(2 * (step + 1) + wg, (step + 1) & 1);
        const char* Ksb = sm + base + (step & 1) * BUFB;
        const char* VTb = Ksb + KSB;
        #pragma unroll
        for (int half = 0; half < 2; half++) {
            float s[8][4];
            #pragma unroll
            for (int nb = 0; nb < 8; nb++) {
                s[nb][0] = s[nb][1] = s[nb][2] = s[nb][3] = 0.0f;
                const char* kr = Ksb + ((half * 8 + nb) * 8 + g) * 144 + i * 4;
                #pragma unroll
                for (int ks = 0; ks < 4; ks++) {
                    uint32_t b0 = *(const uint32_t*)(kr + ks * 32);
                    uint32_t b1 = *(const uint32_t*)(kr + ks * 32 + 16);
                    mma_f16(s[nb], qa[ks], b0, b1);
                }
            }
            #pragma unroll
            for (int ks = 0; ks < 4; ks++) {
                uint32_t pa[4];
                pa[0] = expack(s[2*ks][0],   s[2*ks][1]);
                pa[1] = expack(s[2*ks][2],   s[2*ks][3]);
                pa[2] = expack(s[2*ks+1][0], s[2*ks+1][1]);
                pa[3] = expack(s[2*ks+1][2], s[2*ks+1][3]);
                const char* vr = VTb + g * 272 + i * 4 + (half * 4 + ks) * 32;
                #pragma unroll
                for (int nd = 0; nd < 9; nd++) {
                    uint32_t b0 = *(const uint32_t*)(vr + nd * 8 * 272);
                    uint32_t b1 = *(const uint32_t*)(vr + nd * 8 * 272 + 16);
                    mma_f16(o[nd], pa, b0, b1);
                }
            }
        }
    }

    __syncthreads();
    float* ms = (float*)sm;
    const int slot = (wl * 32 + lane) * 36;
    if (wg == 1) {
        #pragma unroll
        for (int nd = 0; nd < 9; nd++)
            #pragma unroll
            for (int c = 0; c < 4; c++) ms[slot + nd * 4 + c] = o[nd][c];
    }
    __syncthreads();
    if (wg == 0) {
        #pragma unroll
        for (int nd = 0; nd < 9; nd++)
            #pragma unroll
            for (int c = 0; c < 4; c++) o[nd][c] += ms[slot + nd * 4 + c];
        float lpg  = __shfl_sync(0xffffffffu, o[8][0], lane & ~3);
        float lpg8 = __shfl_sync(0xffffffffu, o[8][2], lane & ~3);
        float invg = 1.0f / lpg, inv8 = 1.0f / lpg8;
        const int r0 = n0 + 16 * wl + g;
        uint32_t* ob = (uint32_t*)(g_o16 + (size_t)r0 * DIMc + (h << 6) + 2 * i);
        #pragma unroll
        for (int nd = 0; nd < 8; nd++) {
            ob[nd * 4]              = packh(o[nd][0] * invg, o[nd][1] * invg);
            ob[(8 * DIMc) / 2 + nd * 4] = packh(o[nd][2] * inv8, o[nd][3] * inv8);
        }
    }
}

// ---------------- launch ----------------
extern "C" void kernel_launch(void* const* d_in, const int* in_sizes, int n_in,
                              void* d_out, int out_size) {
    const float* x      = (const float*)d_in[0];
    const float* past_k = (const float*)d_in[1];
    const float* past_v = (const float*)d_in[2];
    const float* qkv_w  = (const float*)d_in[3];
    const float* qkv_b  = (const float*)d_in[4];
    const float* proj_w = (const float*)d_in[5];
    const float* proj_b = (const float*)d_in[6];

    float* out = (float*)d_out;
    float* nk  = out + (size_t)Nq * DIMc;
    float* nv  = nk + (size_t)Hh * 4096 * 64;

    __half *kb, *vtb, *x16, *w16, *pw16, *o16;
    cudaGetSymbolAddress((void**)&kb,   g_kb);
    cudaGetSymbolAddress((void**)&vtb,  g_vtb);
    cudaGetSymbolAddress((void**)&x16,  g_x16);
    cudaGetSymbolAddress((void**)&w16,  g_w16);
    cudaGetSymbolAddress((void**)&pw16, g_pw16);
    cudaGetSymbolAddress((void**)&o16,  g_o16);

    cudaFuncSetAttribute(attn_mma, cudaFuncAttributeMaxDynamicSharedMemorySize, ATTN_SMEM);

    stage1<<<5376, 256>>>(x, qkv_w, proj_w);
    xm2<<<1, 1024>>>();
    qm<<<64, 256>>>(qkv_w, qkv_b);
    mfin<<<1, 64>>>();

    gemm_h16<<<dim3(48, 8), 256>>>(x16, w16, qkv_b, nullptr, 1);

    stagekv<<<dim3(132, 16), 256>>>(past_k, past_v);
    select_topk<<<1, 1024>>>();

    attn_mma<<<dim3(8, 24), 512, ATTN_SMEM>>>(kb, vtb, past_k, past_v, nk, nv);
    gemm_h16<<<dim3(16, 8), 256>>>(o16, pw16, proj_b, out, 0);
}